// round 2
// baseline (speedup 1.0000x reference)
#include <cuda_runtime.h>
#include <math.h>

#define EDIM 1024
#define NSEQ 2048
#define NBATCH 2
#define DH 64
#define NGROUPS 32   /* B * N_BLOCKS * MICRO_HEADS = 2*2*8 */

// Scratch (device globals: no allocation allowed in kernel_launch)
__device__ float g_q[NGROUPS * NSEQ * DH];
__device__ float g_k[NGROUPS * NSEQ * DH];
__device__ float g_v[NGROUPS * NSEQ * DH];
__device__ float g_ctx[NBATCH * NSEQ * EDIM];

// ---------------------------------------------------------------------------
// GEMM: C[r][c] = alpha * (sum_k A[r][k] * W[c][k] + bias[c])
// A: (4096, 1024) row-major, W: (1024, 1024) row-major (both K-contiguous: NT GEMM)
// 128x128 block tile, BK=8, 256 threads, 8x8 microtile, double-buffered smem.
// SCRAMBLE=true: write each output element to its scrambled (b,g,m',n',d) slot.
// ---------------------------------------------------------------------------
template<bool SCRAMBLE>
__global__ __launch_bounds__(256, 2)
void gemm_nt(const float* __restrict__ A, const float* __restrict__ W,
             const float* __restrict__ bias, float* __restrict__ C, float alpha)
{
    __shared__ float As[2][8][132];
    __shared__ float Ws[2][8][132];

    const int tid = threadIdx.x;
    const int tx = tid & 15;
    const int ty = tid >> 4;
    const int rbase = blockIdx.y * 128;
    const int cbase = blockIdx.x * 128;

    const int lr = tid >> 1;          // 0..127 : tile row loaded by this thread
    const int lk = (tid & 1) << 2;    // 0 or 4 : k offset within BK=8

    const float* Ap = A + (size_t)(rbase + lr) * EDIM + lk;
    const float* Wp = W + (size_t)(cbase + lr) * EDIM + lk;

    float acc[8][8];
#pragma unroll
    for (int i = 0; i < 8; i++)
#pragma unroll
        for (int j = 0; j < 8; j++) acc[i][j] = 0.f;

    // prologue: load k-tile 0
    {
        float4 a4 = *(const float4*)Ap;
        float4 w4 = *(const float4*)Wp;
        As[0][lk + 0][lr] = a4.x; As[0][lk + 1][lr] = a4.y;
        As[0][lk + 2][lr] = a4.z; As[0][lk + 3][lr] = a4.w;
        Ws[0][lk + 0][lr] = w4.x; Ws[0][lk + 1][lr] = w4.y;
        Ws[0][lk + 2][lr] = w4.z; Ws[0][lk + 3][lr] = w4.w;
    }
    __syncthreads();

    const int NT = EDIM / 8;  // 128 k-tiles
    int buf = 0;
#pragma unroll 1
    for (int kt = 0; kt < NT; kt++) {
        float4 na, nw;
        const bool pf = (kt + 1 < NT);
        if (pf) {
            na = *(const float4*)(Ap + (size_t)(kt + 1) * 8);
            nw = *(const float4*)(Wp + (size_t)(kt + 1) * 8);
        }
#pragma unroll
        for (int k = 0; k < 8; k++) {
            float4 a0 = *(const float4*)&As[buf][k][ty * 8];
            float4 a1 = *(const float4*)&As[buf][k][ty * 8 + 4];
            float4 b0 = *(const float4*)&Ws[buf][k][tx * 8];
            float4 b1 = *(const float4*)&Ws[buf][k][tx * 8 + 4];
            float ra[8] = {a0.x, a0.y, a0.z, a0.w, a1.x, a1.y, a1.z, a1.w};
            float rb[8] = {b0.x, b0.y, b0.z, b0.w, b1.x, b1.y, b1.z, b1.w};
#pragma unroll
            for (int i = 0; i < 8; i++)
#pragma unroll
                for (int j = 0; j < 8; j++)
                    acc[i][j] = fmaf(ra[i], rb[j], acc[i][j]);
        }
        if (pf) {
            const int nb = buf ^ 1;
            As[nb][lk + 0][lr] = na.x; As[nb][lk + 1][lr] = na.y;
            As[nb][lk + 2][lr] = na.z; As[nb][lk + 3][lr] = na.w;
            Ws[nb][lk + 0][lr] = nw.x; Ws[nb][lk + 1][lr] = nw.y;
            Ws[nb][lk + 2][lr] = nw.z; Ws[nb][lk + 3][lr] = nw.w;
            __syncthreads();
            buf = nb;
        }
    }

    // epilogue
    const int c0 = cbase + tx * 8;
    float bv[8];
#pragma unroll
    for (int j = 0; j < 8; j++) bv[j] = bias[c0 + j];

#pragma unroll
    for (int i = 0; i < 8; i++) {
        const int r = rbase + ty * 8 + i;
#pragma unroll
        for (int h = 0; h < 2; h++) {
            float4 v;
            v.x = alpha * (acc[i][h * 4 + 0] + bv[h * 4 + 0]);
            v.y = alpha * (acc[i][h * 4 + 1] + bv[h * 4 + 1]);
            v.z = alpha * (acc[i][h * 4 + 2] + bv[h * 4 + 2]);
            v.w = alpha * (acc[i][h * 4 + 3] + bv[h * 4 + 3]);
            if (SCRAMBLE) {
                const int cc = c0 + h * 4;
                const int b_ = r >> 11;               // batch
                const int n  = r & (NSEQ - 1);        // token
                const int g  = cc >> 9;               // block (0/1)
                const int mm = (cc >> 6) & 7;         // micro-head
                const int d  = cc & 63;               // head dim (mult of 4)
                const int flat = n * 8 + mm;
                const int mp = flat >> 11;            // scrambled head slot
                const int np = flat & (NSEQ - 1);     // scrambled seq pos
                const size_t dst =
                    ((size_t)((b_ * 2 + g) * 8 + mp) * NSEQ + np) * DH + d;
                *(float4*)(C + dst) = v;
            } else {
                *(float4*)(C + (size_t)r * EDIM + c0 + h * 4) = v;
            }
        }
    }
}

// ---------------------------------------------------------------------------
// Flash attention: 32 independent causal attentions, seqlen 2048, dh=64.
// Br = Bc = 64, 256 threads (16x16), 4x4 microtile of S / O per thread.
// Qs/Ks stored d-major (transposed), Vs natural, P round-trips through smem.
// Writes ctx directly in unscrambled (b, n, e) layout.
// ---------------------------------------------------------------------------
#define ATTN_SMEM (4 * 64 * 68 * 4)

__global__ __launch_bounds__(256, 2)
void attn_kernel(float* __restrict__ ctx)
{
    extern __shared__ float sm[];
    float* Qs = sm;                 // [64 d][68]  Qs[d][qi]
    float* Ks = Qs + 64 * 68;       // [64 d][68]  Ks[d][kj]
    float* Vs = Ks + 64 * 68;       // [64 kj][68] Vs[kj][d]
    float* Ps = Vs + 64 * 68;       // [64 qi][68] Ps[qi][kj]

    const int tid = threadIdx.x;
    const int tx = tid & 15;
    const int ty = tid >> 4;
    // launch long diagonals first (qblk = 31 has 32 kv-tiles, qblk = 0 has 1)
    const int qblk = (int)gridDim.x - 1 - (int)blockIdx.x;
    const int bgm  = blockIdx.y;    // (b*2+g)*8 + m'

    const float* Qb = g_q + (size_t)bgm * NSEQ * DH;
    const float* Kb = g_k + (size_t)bgm * NSEQ * DH;
    const float* Vb = g_v + (size_t)bgm * NSEQ * DH;

    // load Q tile (transposed to d-major)
#pragma unroll
    for (int rep = 0; rep < 4; rep++) {
        const int idx = rep * 256 + tid;
        const int qi = idx >> 4;
        const int f = (idx & 15) << 2;
        float4 v = *(const float4*)(Qb + (size_t)(qblk * 64 + qi) * DH + f);
        Qs[(f + 0) * 68 + qi] = v.x;
        Qs[(f + 1) * 68 + qi] = v.y;
        Qs[(f + 2) * 68 + qi] = v.z;
        Qs[(f + 3) * 68 + qi] = v.w;
    }

    float m_i[4], l_i[4], O[4][4];
#pragma unroll
    for (int i = 0; i < 4; i++) {
        m_i[i] = -INFINITY;
        l_i[i] = 0.f;
#pragma unroll
        for (int j = 0; j < 4; j++) O[i][j] = 0.f;
    }

    const int nkv = qblk + 1;
    for (int jb = 0; jb < nkv; jb++) {
        __syncthreads();  // (A) prev iter done reading Ks/Vs/Ps; Qs stores done
        // load K transposed + V natural
#pragma unroll
        for (int rep = 0; rep < 4; rep++) {
            const int idx = rep * 256 + tid;
            const int kj = idx >> 4;
            const int f = (idx & 15) << 2;
            float4 kv = *(const float4*)(Kb + (size_t)(jb * 64 + kj) * DH + f);
            Ks[(f + 0) * 68 + kj] = kv.x;
            Ks[(f + 1) * 68 + kj] = kv.y;
            Ks[(f + 2) * 68 + kj] = kv.z;
            Ks[(f + 3) * 68 + kj] = kv.w;
            float4 vv = *(const float4*)(Vb + (size_t)(jb * 64 + kj) * DH + f);
            *(float4*)&Vs[kj * 68 + f] = vv;
        }
        __syncthreads();  // (B) tiles ready

        // S = Q K^T (Q already pre-scaled by dh^-0.5)
        float S[4][4];
#pragma unroll
        for (int i = 0; i < 4; i++)
#pragma unroll
            for (int j = 0; j < 4; j++) S[i][j] = 0.f;

#pragma unroll 8
        for (int d = 0; d < 64; d++) {
            float4 q4 = *(const float4*)&Qs[d * 68 + ty * 4];
            float4 k4 = *(const float4*)&Ks[d * 68 + tx * 4];
            float rq[4] = {q4.x, q4.y, q4.z, q4.w};
            float rk[4] = {k4.x, k4.y, k4.z, k4.w};
#pragma unroll
            for (int i = 0; i < 4; i++)
#pragma unroll
                for (int j = 0; j < 4; j++)
                    S[i][j] = fmaf(rq[i], rk[j], S[i][j]);
        }

        // causal mask (only the diagonal block needs it)
        if (jb == qblk) {
#pragma unroll
            for (int i = 0; i < 4; i++) {
                const int qg = ty * 4 + i;
#pragma unroll
                for (int j = 0; j < 4; j++) {
                    const int kg = tx * 4 + j;
                    if (kg > qg) S[i][j] = -INFINITY;
                }
            }
        }

        // online softmax (row-mates = 16 contiguous lanes: butterfly over 4 bits)
#pragma unroll
        for (int i = 0; i < 4; i++) {
            float rmax = fmaxf(fmaxf(S[i][0], S[i][1]), fmaxf(S[i][2], S[i][3]));
#pragma unroll
            for (int off = 1; off < 16; off <<= 1)
                rmax = fmaxf(rmax, __shfl_xor_sync(0xffffffffu, rmax, off));
            const float mnew = fmaxf(m_i[i], rmax);
            const float a = __expf(m_i[i] - mnew);   // first iter: exp(-inf)=0
            float rs = 0.f;
#pragma unroll
            for (int j = 0; j < 4; j++) {
                const float p = __expf(S[i][j] - mnew);
                S[i][j] = p;
                rs += p;
            }
#pragma unroll
            for (int off = 1; off < 16; off <<= 1)
                rs += __shfl_xor_sync(0xffffffffu, rs, off);
            l_i[i] = l_i[i] * a + rs;
            m_i[i] = mnew;
#pragma unroll
            for (int j = 0; j < 4; j++) O[i][j] *= a;
        }

        // store P
#pragma unroll
        for (int i = 0; i < 4; i++) {
            float4 p;
            p.x = S[i][0]; p.y = S[i][1]; p.z = S[i][2]; p.w = S[i][3];
            *(float4*)&Ps[(ty * 4 + i) * 68 + tx * 4] = p;
        }
        __syncthreads();  // (C) Ps ready

        // O += P @ V
#pragma unroll 4
        for (int kb = 0; kb < 16; kb++) {
            float pr[4][4];
#pragma unroll
            for (int i = 0; i < 4; i++) {
                float4 t = *(const float4*)&Ps[(ty * 4 + i) * 68 + kb * 4];
                pr[i][0] = t.x; pr[i][1] = t.y; pr[i][2] = t.z; pr[i][3] = t.w;
            }
#pragma unroll
            for (int u = 0; u < 4; u++) {
                float4 vv = *(const float4*)&Vs[(kb * 4 + u) * 68 + tx * 4];
#pragma unroll
                for (int i = 0; i < 4; i++) {
                    O[i][0] = fmaf(pr[i][u], vv.x, O[i][0]);
                    O[i][1] = fmaf(pr[i][u], vv.y, O[i][1]);
                    O[i][2] = fmaf(pr[i][u], vv.z, O[i][2]);
                    O[i][3] = fmaf(pr[i][u], vv.w, O[i][3]);
                }
            }
        }
    }

    // epilogue: normalize and write ctx UNSCRAMBLED: (b, n, g*512 + m*64 + d)
    const int b_ = bgm >> 4;
    const int g  = (bgm >> 3) & 1;
    const int mp = bgm & 7;
#pragma unroll
    for (int i = 0; i < 4; i++) {
        const int np = qblk * 64 + ty * 4 + i;
        const float inv = 1.0f / l_i[i];
        const int flat = mp * NSEQ + np;
        const int n = flat >> 3;
        const int mm = flat & 7;
        const int col = g * 512 + mm * 64 + tx * 4;
        float4 o;
        o.x = O[i][0] * inv; o.y = O[i][1] * inv;
        o.z = O[i][2] * inv; o.w = O[i][3] * inv;
        *(float4*)(ctx + (size_t)(b_ * NSEQ + n) * EDIM + col) = o;
    }
}

// ---------------------------------------------------------------------------

extern "C" void kernel_launch(void* const* d_in, const int* in_sizes, int n_in,
                              void* d_out, int out_size) {
    (void)in_sizes; (void)n_in; (void)out_size;
    const float* x  = (const float*)d_in[0];
    const float* Wq = (const float*)d_in[1];
    const float* bq = (const float*)d_in[2];
    const float* Wk = (const float*)d_in[3];
    const float* bk = (const float*)d_in[4];
    const float* Wv = (const float*)d_in[5];
    const float* bv = (const float*)d_in[6];
    const float* Wo = (const float*)d_in[7];
    const float* bo = (const float*)d_in[8];
    float* out = (float*)d_out;

    float *pq, *pk, *pv, *pctx;
    cudaGetSymbolAddress((void**)&pq,   g_q);
    cudaGetSymbolAddress((void**)&pk,   g_k);
    cudaGetSymbolAddress((void**)&pv,   g_v);
    cudaGetSymbolAddress((void**)&pctx, g_ctx);

    cudaFuncSetAttribute(attn_kernel,
                         cudaFuncAttributeMaxDynamicSharedMemorySize, ATTN_SMEM);

    const dim3 gb(EDIM / 128, (NBATCH * NSEQ) / 128);  // (8, 32)
    const dim3 tb(256);
    const float scale = 0.125f;  // dh^-0.5, folded into Q

    gemm_nt<true ><<<gb, tb>>>(x, Wq, bq, pq, scale);
    gemm_nt<true ><<<gb, tb>>>(x, Wk, bk, pk, 1.0f);
    gemm_nt<true ><<<gb, tb>>>(x, Wv, bv, pv, 1.0f);

    attn_kernel<<<dim3(NSEQ / 64, NGROUPS), 256, ATTN_SMEM>>>(pctx);

    gemm_nt<false><<<gb, tb>>>(pctx, Wo, bo, out, 1.0f);
}

// round 4
// speedup vs baseline: 1.4506x; 1.4506x over previous
#include <cuda_runtime.h>
#include <math.h>
#include <stdint.h>

#define EDIM 1024
#define NSEQ 2048
#define NBATCH 2
#define DH 64
#define NGROUPS 32   /* B * N_BLOCKS * MICRO_HEADS = 2*2*8 */

// Scratch (device globals: no allocation allowed in kernel_launch)
__device__ float g_q[NGROUPS * NSEQ * DH];
__device__ float g_k[NGROUPS * NSEQ * DH];
__device__ float g_v[NGROUPS * NSEQ * DH];
__device__ float g_ctx[NBATCH * NSEQ * EDIM];

// ---------------------------------------------------------------------------
// helpers
// ---------------------------------------------------------------------------
__device__ __forceinline__ float tf32_rna(float x) {
    uint32_t u;
    asm("cvt.rna.tf32.f32 %0, %1;" : "=r"(u) : "f"(x));
    return __uint_as_float(u);
}

__device__ __forceinline__ void mma_tf32(float* c, const uint32_t* a, const uint32_t* b) {
    asm volatile(
        "mma.sync.aligned.m16n8k8.row.col.f32.tf32.tf32.f32 "
        "{%0,%1,%2,%3}, {%4,%5,%6,%7}, {%8,%9}, {%0,%1,%2,%3};"
        : "+f"(c[0]), "+f"(c[1]), "+f"(c[2]), "+f"(c[3])
        : "r"(a[0]), "r"(a[1]), "r"(a[2]), "r"(a[3]), "r"(b[0]), "r"(b[1]));
}

// ---------------------------------------------------------------------------
// tf32 HMMA GEMM: C[r][c] = alpha * (sum_k A[r][k] * W[c][k] + bias[c])
// A:(4096,1024) W:(1024,1024) row-major K-contiguous (NT GEMM).
// BM=256 BN=128 BK=16, 256 threads, 8 warps (4m x 2n), 64x64 per warp.
// smem row stride 20 floats -> conflict-free frag LDS and fill STS.128.
// ---------------------------------------------------------------------------
#define BM 256
#define BN 128
#define BK 16
#define KST 20                              /* smem row stride (floats) */
#define NKT (EDIM / BK)                     /* 64 */
#define STAGEF (BM * KST + BN * KST)        /* 7680 floats per stage */
#define GEMM_SMEM (2 * STAGEF * 4)          /* 61440 bytes */

struct GemmJob  { const float* W; const float* bias; float* C; float alpha; };
struct GemmJobs { GemmJob j[3]; };

template<bool SCRAMBLE>
__device__ __forceinline__ void gemm_core(
    const float* __restrict__ A, const float* __restrict__ W,
    const float* __restrict__ bias, float* __restrict__ C, float alpha)
{
    extern __shared__ float sh[];
    const int tid  = threadIdx.x;
    const int lane = tid & 31, wid = tid >> 5;
    const int g = lane >> 2, t = lane & 3;          // mma group / in-group id
    const int wm = (wid >> 1) * 64;                  // warp m offset (0..192)
    const int wn = (wid & 1) * 64;                   // warp n offset (0/64)
    const int rbase = blockIdx.y * BM;
    const int cbase = blockIdx.x * BN;

    float* Asb[2] = { sh,              sh + STAGEF };
    float* Bsb[2] = { sh + BM * KST,   sh + STAGEF + BM * KST };

    float acc[4][8][4];
#pragma unroll
    for (int mt = 0; mt < 4; mt++)
#pragma unroll
        for (int nt = 0; nt < 8; nt++)
#pragma unroll
            for (int q = 0; q < 4; q++) acc[mt][nt][q] = 0.f;

    // prologue: fill stage 0 (k-tile 0)
    {
#pragma unroll
        for (int i = 0; i < 4; i++) {                // A: 1024 float4
            const int idx = tid + i * 256;
            const int r = idx >> 2, f = idx & 3;
            float4 v = *(const float4*)(A + (size_t)(rbase + r) * EDIM + f * 4);
            v.x = tf32_rna(v.x); v.y = tf32_rna(v.y);
            v.z = tf32_rna(v.z); v.w = tf32_rna(v.w);
            *(float4*)&Asb[0][r * KST + f * 4] = v;
        }
#pragma unroll
        for (int i = 0; i < 2; i++) {                // B: 512 float4
            const int idx = tid + i * 256;
            const int r = idx >> 2, f = idx & 3;
            float4 v = *(const float4*)(W + (size_t)(cbase + r) * EDIM + f * 4);
            v.x = tf32_rna(v.x); v.y = tf32_rna(v.y);
            v.z = tf32_rna(v.z); v.w = tf32_rna(v.w);
            *(float4*)&Bsb[0][r * KST + f * 4] = v;
        }
    }
    __syncthreads();

    int buf = 0;
#pragma unroll 1
    for (int kt = 0; kt < NKT; kt++) {
        float4 pa[4], pb[2];
        const bool pf = (kt + 1 < NKT);
        if (pf) {
#pragma unroll
            for (int i = 0; i < 4; i++) {
                const int idx = tid + i * 256;
                const int r = idx >> 2, f = idx & 3;
                pa[i] = *(const float4*)(A + (size_t)(rbase + r) * EDIM + (kt + 1) * BK + f * 4);
            }
#pragma unroll
            for (int i = 0; i < 2; i++) {
                const int idx = tid + i * 256;
                const int r = idx >> 2, f = idx & 3;
                pb[i] = *(const float4*)(W + (size_t)(cbase + r) * EDIM + (kt + 1) * BK + f * 4);
            }
        }

        const float* as = Asb[buf];
        const float* bs = Bsb[buf];
#pragma unroll
        for (int ks = 0; ks < 2; ks++) {
            uint32_t af[4][4], bf[8][2];
#pragma unroll
            for (int mt = 0; mt < 4; mt++) {
                const uint32_t* p =
                    (const uint32_t*)&as[(wm + mt * 16 + g) * KST + ks * 8 + t];
                af[mt][0] = p[0];            // (row g,   col t)
                af[mt][1] = p[8 * KST];      // (row g+8, col t)
                af[mt][2] = p[4];            // (row g,   col t+4)
                af[mt][3] = p[8 * KST + 4];  // (row g+8, col t+4)
            }
#pragma unroll
            for (int nt = 0; nt < 8; nt++) {
                const uint32_t* p =
                    (const uint32_t*)&bs[(wn + nt * 8 + g) * KST + ks * 8 + t];
                bf[nt][0] = p[0];            // (k t,   n g)
                bf[nt][1] = p[4];            // (k t+4, n g)
            }
#pragma unroll
            for (int mt = 0; mt < 4; mt++)
#pragma unroll
                for (int nt = 0; nt < 8; nt++)
                    mma_tf32(acc[mt][nt], af[mt], bf[nt]);
        }

        if (pf) {
            const int nb = buf ^ 1;
#pragma unroll
            for (int i = 0; i < 4; i++) {
                const int idx = tid + i * 256;
                const int r = idx >> 2, f = idx & 3;
                float4 v = pa[i];
                v.x = tf32_rna(v.x); v.y = tf32_rna(v.y);
                v.z = tf32_rna(v.z); v.w = tf32_rna(v.w);
                *(float4*)&Asb[nb][r * KST + f * 4] = v;
            }
#pragma unroll
            for (int i = 0; i < 2; i++) {
                const int idx = tid + i * 256;
                const int r = idx >> 2, f = idx & 3;
                float4 v = pb[i];
                v.x = tf32_rna(v.x); v.y = tf32_rna(v.y);
                v.z = tf32_rna(v.z); v.w = tf32_rna(v.w);
                *(float4*)&Bsb[nb][r * KST + f * 4] = v;
            }
            __syncthreads();
            buf = nb;
        }
    }

    // epilogue: c0=(g,2t) c1=(g,2t+1) c2=(g+8,2t) c3=(g+8,2t+1) per fragment
#pragma unroll
    for (int nt = 0; nt < 8; nt++) {
        const int col = cbase + wn + nt * 8 + 2 * t;
        const float2 bb = *(const float2*)&bias[col];
#pragma unroll
        for (int mt = 0; mt < 4; mt++) {
#pragma unroll
            for (int h = 0; h < 2; h++) {
                const int r = rbase + wm + mt * 16 + g + h * 8;
                float2 v;
                v.x = alpha * (acc[mt][nt][h * 2 + 0] + bb.x);
                v.y = alpha * (acc[mt][nt][h * 2 + 1] + bb.y);
                if (SCRAMBLE) {
                    const int b_ = r >> 11;               // batch
                    const int n  = r & (NSEQ - 1);        // token
                    const int gb = col >> 9;              // block (0/1)
                    const int mm = (col >> 6) & 7;        // micro-head
                    const int dd = col & 63;              // head dim (even)
                    const int flat = n * 8 + mm;
                    const int mp = flat >> 11;
                    const int np = flat & (NSEQ - 1);
                    *(float2*)(C + ((size_t)((b_ * 2 + gb) * 8 + mp) * NSEQ + np) * DH + dd) = v;
                } else {
                    *(float2*)(C + (size_t)r * EDIM + col) = v;
                }
            }
        }
    }
}

template<bool SCRAMBLE>
__global__ __launch_bounds__(256, 1)
void gemm_mma(const float* __restrict__ A, GemmJobs jobs)
{
    const GemmJob jb = jobs.j[blockIdx.z];
    gemm_core<SCRAMBLE>(A, jb.W, jb.bias, jb.C, jb.alpha);
}

// ---------------------------------------------------------------------------
// Flash attention (unchanged from passing R1 kernel): 32 causal attentions,
// seqlen 2048, dh=64. Br=Bc=64, 256 threads, 4x4 microtiles, fp32.
// ---------------------------------------------------------------------------
#define ATTN_SMEM (4 * 64 * 68 * 4)

__global__ __launch_bounds__(256, 2)
void attn_kernel(float* __restrict__ ctx)
{
    extern __shared__ float smf[];
    float* Qs = smf;
    float* Ks = Qs + 64 * 68;
    float* Vs = Ks + 64 * 68;
    float* Ps = Vs + 64 * 68;

    const int tid = threadIdx.x;
    const int tx = tid & 15;
    const int ty = tid >> 4;
    const int qblk = (int)gridDim.x - 1 - (int)blockIdx.x;
    const int bgm  = blockIdx.y;

    const float* Qb = g_q + (size_t)bgm * NSEQ * DH;
    const float* Kb = g_k + (size_t)bgm * NSEQ * DH;
    const float* Vb = g_v + (size_t)bgm * NSEQ * DH;

#pragma unroll
    for (int rep = 0; rep < 4; rep++) {
        const int idx = rep * 256 + tid;
        const int qi = idx >> 4;
        const int f = (idx & 15) << 2;
        float4 v = *(const float4*)(Qb + (size_t)(qblk * 64 + qi) * DH + f);
        Qs[(f + 0) * 68 + qi] = v.x;
        Qs[(f + 1) * 68 + qi] = v.y;
        Qs[(f + 2) * 68 + qi] = v.z;
        Qs[(f + 3) * 68 + qi] = v.w;
    }

    float m_i[4], l_i[4], O[4][4];
#pragma unroll
    for (int i = 0; i < 4; i++) {
        m_i[i] = -INFINITY;
        l_i[i] = 0.f;
#pragma unroll
        for (int j = 0; j < 4; j++) O[i][j] = 0.f;
    }

    const int nkv = qblk + 1;
    for (int jb = 0; jb < nkv; jb++) {
        __syncthreads();
#pragma unroll
        for (int rep = 0; rep < 4; rep++) {
            const int idx = rep * 256 + tid;
            const int kj = idx >> 4;
            const int f = (idx & 15) << 2;
            float4 kv = *(const float4*)(Kb + (size_t)(jb * 64 + kj) * DH + f);
            Ks[(f + 0) * 68 + kj] = kv.x;
            Ks[(f + 1) * 68 + kj] = kv.y;
            Ks[(f + 2) * 68 + kj] = kv.z;
            Ks[(f + 3) * 68 + kj] = kv.w;
            float4 vv = *(const float4*)(Vb + (size_t)(jb * 64 + kj) * DH + f);
            *(float4*)&Vs[kj * 68 + f] = vv;
        }
        __syncthreads();

        float S[4][4];
#pragma unroll
        for (int i = 0; i < 4; i++)
#pragma unroll
            for (int j = 0; j < 4; j++) S[i][j] = 0.f;

#pragma unroll 8
        for (int d = 0; d < 64; d++) {
            float4 q4 = *(const float4*)&Qs[d * 68 + ty * 4];
            float4 k4 = *(const float4*)&Ks[d * 68 + tx * 4];
            float rq[4] = {q4.x, q4.y, q4.z, q4.w};
            float rk[4] = {k4.x, k4.y, k4.z, k4.w};
#pragma unroll
            for (int i = 0; i < 4; i++)
#pragma unroll
                for (int j = 0; j < 4; j++)
                    S[i][j] = fmaf(rq[i], rk[j], S[i][j]);
        }

        if (jb == qblk) {
#pragma unroll
            for (int i = 0; i < 4; i++) {
                const int qg = ty * 4 + i;
#pragma unroll
                for (int j = 0; j < 4; j++) {
                    const int kg = tx * 4 + j;
                    if (kg > qg) S[i][j] = -INFINITY;
                }
            }
        }

#pragma unroll
        for (int i = 0; i < 4; i++) {
            float rmax = fmaxf(fmaxf(S[i][0], S[i][1]), fmaxf(S[i][2], S[i][3]));
#pragma unroll
            for (int off = 1; off < 16; off <<= 1)
                rmax = fmaxf(rmax, __shfl_xor_sync(0xffffffffu, rmax, off));
            const float mnew = fmaxf(m_i[i], rmax);
            const float a = __expf(m_i[i] - mnew);
            float rs = 0.f;
#pragma unroll
            for (int j = 0; j < 4; j++) {
                const float p = __expf(S[i][j] - mnew);
                S[i][j] = p;
                rs += p;
            }
#pragma unroll
            for (int off = 1; off < 16; off <<= 1)
                rs += __shfl_xor_sync(0xffffffffu, rs, off);
            l_i[i] = l_i[i] * a + rs;
            m_i[i] = mnew;
#pragma unroll
            for (int j = 0; j < 4; j++) O[i][j] *= a;
        }

#pragma unroll
        for (int i = 0; i < 4; i++) {
            float4 p;
            p.x = S[i][0]; p.y = S[i][1]; p.z = S[i][2]; p.w = S[i][3];
            *(float4*)&Ps[(ty * 4 + i) * 68 + tx * 4] = p;
        }
        __syncthreads();

#pragma unroll 4
        for (int kb = 0; kb < 16; kb++) {
            float pr[4][4];
#pragma unroll
            for (int i = 0; i < 4; i++) {
                float4 t = *(const float4*)&Ps[(ty * 4 + i) * 68 + kb * 4];
                pr[i][0] = t.x; pr[i][1] = t.y; pr[i][2] = t.z; pr[i][3] = t.w;
            }
#pragma unroll
            for (int u = 0; u < 4; u++) {
                float4 vv = *(const float4*)&Vs[(kb * 4 + u) * 68 + tx * 4];
#pragma unroll
                for (int i = 0; i < 4; i++) {
                    O[i][0] = fmaf(pr[i][u], vv.x, O[i][0]);
                    O[i][1] = fmaf(pr[i][u], vv.y, O[i][1]);
                    O[i][2] = fmaf(pr[i][u], vv.z, O[i][2]);
                    O[i][3] = fmaf(pr[i][u], vv.w, O[i][3]);
                }
            }
        }
    }

    const int b_ = bgm >> 4;
    const int g  = (bgm >> 3) & 1;
    const int mp = bgm & 7;
#pragma unroll
    for (int i = 0; i < 4; i++) {
        const int np = qblk * 64 + ty * 4 + i;
        const float inv = 1.0f / l_i[i];
        const int flat = mp * NSEQ + np;
        const int n = flat >> 3;
        const int mm = flat & 7;
        const int col = g * 512 + mm * 64 + tx * 4;
        float4 o;
        o.x = O[i][0] * inv; o.y = O[i][1] * inv;
        o.z = O[i][2] * inv; o.w = O[i][3] * inv;
        *(float4*)(ctx + (size_t)(b_ * NSEQ + n) * EDIM + col) = o;
    }
}

// ---------------------------------------------------------------------------

extern "C" void kernel_launch(void* const* d_in, const int* in_sizes, int n_in,
                              void* d_out, int out_size) {
    (void)in_sizes; (void)n_in; (void)out_size;
    const float* x  = (const float*)d_in[0];
    const float* Wq = (const float*)d_in[1];
    const float* bq = (const float*)d_in[2];
    const float* Wk = (const float*)d_in[3];
    const float* bk = (const float*)d_in[4];
    const float* Wv = (const float*)d_in[5];
    const float* bv = (const float*)d_in[6];
    const float* Wo = (const float*)d_in[7];
    const float* bo = (const float*)d_in[8];
    float* out = (float*)d_out;

    float *pq, *pk, *pv, *pctx;
    cudaGetSymbolAddress((void**)&pq,   g_q);
    cudaGetSymbolAddress((void**)&pk,   g_k);
    cudaGetSymbolAddress((void**)&pv,   g_v);
    cudaGetSymbolAddress((void**)&pctx, g_ctx);

    cudaFuncSetAttribute(gemm_mma<true>,
                         cudaFuncAttributeMaxDynamicSharedMemorySize, GEMM_SMEM);
    cudaFuncSetAttribute(gemm_mma<false>,
                         cudaFuncAttributeMaxDynamicSharedMemorySize, GEMM_SMEM);
    cudaFuncSetAttribute(attn_kernel,
                         cudaFuncAttributeMaxDynamicSharedMemorySize, ATTN_SMEM);

    const float scale = 0.125f;  // dh^-0.5, folded into Q (and its bias)

    GemmJobs qkv;
    qkv.j[0] = { Wq, bq, pq, scale };
    qkv.j[1] = { Wk, bk, pk, 1.0f };
    qkv.j[2] = { Wv, bv, pv, 1.0f };
    gemm_mma<true><<<dim3(EDIM / BN, (NBATCH * NSEQ) / BM, 3), 256, GEMM_SMEM>>>(x, qkv);

    attn_kernel<<<dim3(NSEQ / 64, NGROUPS), 256, ATTN_SMEM>>>(pctx);

    GemmJobs oj;
    oj.j[0] = { Wo, bo, out, 1.0f };
    oj.j[1] = oj.j[0];
    oj.j[2] = oj.j[0];
    gemm_mma<false><<<dim3(EDIM / BN, (NBATCH * NSEQ) / BM, 1), 256, GEMM_SMEM>>>(pctx, oj);
}

// round 6
// speedup vs baseline: 2.4775x; 1.7079x over previous
#include <cuda_runtime.h>
#include <math.h>
#include <stdint.h>

#define EDIM 1024
#define NSEQ 2048
#define NBATCH 2
#define DH 64
#define NGROUPS 32   /* B * N_BLOCKS * MICRO_HEADS = 2*2*8 */

// Scratch (device globals: no allocation allowed in kernel_launch)
__device__ float g_q[NGROUPS * NSEQ * DH];
__device__ float g_k[NGROUPS * NSEQ * DH];
__device__ float g_v[NGROUPS * NSEQ * DH];
__device__ float g_ctx[NBATCH * NSEQ * EDIM];

// ---------------------------------------------------------------------------
// helpers
// ---------------------------------------------------------------------------
__device__ __forceinline__ float tf32_rna(float x) {
    uint32_t u;
    asm("cvt.rna.tf32.f32 %0, %1;" : "=r"(u) : "f"(x));
    return __uint_as_float(u);
}

__device__ __forceinline__ void mma_tf32(float* c, const uint32_t* a, const uint32_t* b) {
    asm volatile(
        "mma.sync.aligned.m16n8k8.row.col.f32.tf32.tf32.f32 "
        "{%0,%1,%2,%3}, {%4,%5,%6,%7}, {%8,%9}, {%0,%1,%2,%3};"
        : "+f"(c[0]), "+f"(c[1]), "+f"(c[2]), "+f"(c[3])
        : "r"(a[0]), "r"(a[1]), "r"(a[2]), "r"(a[3]), "r"(b[0]), "r"(b[1]));
}

__device__ __forceinline__ uint32_t smem_u32(const void* p) {
    uint32_t a;
    asm("{ .reg .u64 t; cvta.to.shared.u64 t, %1; cvt.u32.u64 %0, t; }" : "=r"(a) : "l"(p));
    return a;
}

__device__ __forceinline__ void cp_async16(uint32_t dst, const void* src) {
    asm volatile("cp.async.cg.shared.global [%0], [%1], 16;" :: "r"(dst), "l"(src));
}
__device__ __forceinline__ void cp_commit() {
    asm volatile("cp.async.commit_group;" ::: "memory");
}
template<int N>
__device__ __forceinline__ void cp_wait() {
    asm volatile("cp.async.wait_group %0;" :: "n"(N) : "memory");
}

// ---------------------------------------------------------------------------
// tf32 HMMA GEMM (unchanged from passing R3 kernel, except: scrambled epilogue
// stores are RNA-rounded to tf32 so attention MMA operands carry no RZ bias).
// C[r][c] = alpha * (sum_k A[r][k] * W[c][k] + bias[c])
// BM=256 BN=128 BK=16, 256 threads, 8 warps (4m x 2n), 64x64 per warp.
// ---------------------------------------------------------------------------
#define BM 256
#define BN 128
#define BK 16
#define KST 20
#define NKT (EDIM / BK)
#define STAGEF (BM * KST + BN * KST)
#define GEMM_SMEM (2 * STAGEF * 4)

struct GemmJob  { const float* W; const float* bias; float* C; float alpha; };
struct GemmJobs { GemmJob j[3]; };

template<bool SCRAMBLE>
__device__ __forceinline__ void gemm_core(
    const float* __restrict__ A, const float* __restrict__ W,
    const float* __restrict__ bias, float* __restrict__ C, float alpha)
{
    extern __shared__ float sh[];
    const int tid  = threadIdx.x;
    const int lane = tid & 31, wid = tid >> 5;
    const int g = lane >> 2, t = lane & 3;
    const int wm = (wid >> 1) * 64;
    const int wn = (wid & 1) * 64;
    const int rbase = blockIdx.y * BM;
    const int cbase = blockIdx.x * BN;

    float* Asb[2] = { sh,              sh + STAGEF };
    float* Bsb[2] = { sh + BM * KST,   sh + STAGEF + BM * KST };

    float acc[4][8][4];
#pragma unroll
    for (int mt = 0; mt < 4; mt++)
#pragma unroll
        for (int nt = 0; nt < 8; nt++)
#pragma unroll
            for (int q = 0; q < 4; q++) acc[mt][nt][q] = 0.f;

    {
#pragma unroll
        for (int i = 0; i < 4; i++) {
            const int idx = tid + i * 256;
            const int r = idx >> 2, f = idx & 3;
            float4 v = *(const float4*)(A + (size_t)(rbase + r) * EDIM + f * 4);
            v.x = tf32_rna(v.x); v.y = tf32_rna(v.y);
            v.z = tf32_rna(v.z); v.w = tf32_rna(v.w);
            *(float4*)&Asb[0][r * KST + f * 4] = v;
        }
#pragma unroll
        for (int i = 0; i < 2; i++) {
            const int idx = tid + i * 256;
            const int r = idx >> 2, f = idx & 3;
            float4 v = *(const float4*)(W + (size_t)(cbase + r) * EDIM + f * 4);
            v.x = tf32_rna(v.x); v.y = tf32_rna(v.y);
            v.z = tf32_rna(v.z); v.w = tf32_rna(v.w);
            *(float4*)&Bsb[0][r * KST + f * 4] = v;
        }
    }
    __syncthreads();

    int buf = 0;
#pragma unroll 1
    for (int kt = 0; kt < NKT; kt++) {
        float4 pa[4], pb[2];
        const bool pf = (kt + 1 < NKT);
        if (pf) {
#pragma unroll
            for (int i = 0; i < 4; i++) {
                const int idx = tid + i * 256;
                const int r = idx >> 2, f = idx & 3;
                pa[i] = *(const float4*)(A + (size_t)(rbase + r) * EDIM + (kt + 1) * BK + f * 4);
            }
#pragma unroll
            for (int i = 0; i < 2; i++) {
                const int idx = tid + i * 256;
                const int r = idx >> 2, f = idx & 3;
                pb[i] = *(const float4*)(W + (size_t)(cbase + r) * EDIM + (kt + 1) * BK + f * 4);
            }
        }

        const float* as = Asb[buf];
        const float* bs = Bsb[buf];
#pragma unroll
        for (int ks = 0; ks < 2; ks++) {
            uint32_t af[4][4], bf[8][2];
#pragma unroll
            for (int mt = 0; mt < 4; mt++) {
                const uint32_t* p =
                    (const uint32_t*)&as[(wm + mt * 16 + g) * KST + ks * 8 + t];
                af[mt][0] = p[0];
                af[mt][1] = p[8 * KST];
                af[mt][2] = p[4];
                af[mt][3] = p[8 * KST + 4];
            }
#pragma unroll
            for (int nt = 0; nt < 8; nt++) {
                const uint32_t* p =
                    (const uint32_t*)&bs[(wn + nt * 8 + g) * KST + ks * 8 + t];
                bf[nt][0] = p[0];
                bf[nt][1] = p[4];
            }
#pragma unroll
            for (int mt = 0; mt < 4; mt++)
#pragma unroll
                for (int nt = 0; nt < 8; nt++)
                    mma_tf32(acc[mt][nt], af[mt], bf[nt]);
        }

        if (pf) {
            const int nb = buf ^ 1;
#pragma unroll
            for (int i = 0; i < 4; i++) {
                const int idx = tid + i * 256;
                const int r = idx >> 2, f = idx & 3;
                float4 v = pa[i];
                v.x = tf32_rna(v.x); v.y = tf32_rna(v.y);
                v.z = tf32_rna(v.z); v.w = tf32_rna(v.w);
                *(float4*)&Asb[nb][r * KST + f * 4] = v;
            }
#pragma unroll
            for (int i = 0; i < 2; i++) {
                const int idx = tid + i * 256;
                const int r = idx >> 2, f = idx & 3;
                float4 v = pb[i];
                v.x = tf32_rna(v.x); v.y = tf32_rna(v.y);
                v.z = tf32_rna(v.z); v.w = tf32_rna(v.w);
                *(float4*)&Bsb[nb][r * KST + f * 4] = v;
            }
            __syncthreads();
            buf = nb;
        }
    }

#pragma unroll
    for (int nt = 0; nt < 8; nt++) {
        const int col = cbase + wn + nt * 8 + 2 * t;
        const float2 bb = *(const float2*)&bias[col];
#pragma unroll
        for (int mt = 0; mt < 4; mt++) {
#pragma unroll
            for (int h = 0; h < 2; h++) {
                const int r = rbase + wm + mt * 16 + g + h * 8;
                float2 v;
                v.x = alpha * (acc[mt][nt][h * 2 + 0] + bb.x);
                v.y = alpha * (acc[mt][nt][h * 2 + 1] + bb.y);
                if (SCRAMBLE) {
                    // RNA-round Q/K/V so attention tf32 MMAs see exact operands
                    v.x = tf32_rna(v.x); v.y = tf32_rna(v.y);
                    const int b_ = r >> 11;
                    const int n  = r & (NSEQ - 1);
                    const int gb = col >> 9;
                    const int mm = (col >> 6) & 7;
                    const int dd = col & 63;
                    const int flat = n * 8 + mm;
                    const int mp = flat >> 11;
                    const int np = flat & (NSEQ - 1);
                    *(float2*)(C + ((size_t)((b_ * 2 + gb) * 8 + mp) * NSEQ + np) * DH + dd) = v;
                } else {
                    *(float2*)(C + (size_t)r * EDIM + col) = v;
                }
            }
        }
    }
}

template<bool SCRAMBLE>
__global__ __launch_bounds__(256, 1)
void gemm_mma(const float* __restrict__ A, GemmJobs jobs)
{
    const GemmJob jb = jobs.j[blockIdx.z];
    gemm_core<SCRAMBLE>(A, jb.W, jb.bias, jb.C, jb.alpha);
}

// ---------------------------------------------------------------------------
// Flash attention on tf32 HMMA. Br=128 (8 warps x m16), Bc=64, dh=64.
// cp.async double-buffered K/V; Q fragments in registers; P smem round-trip
// (warp-private -> __syncwarp only). All MMA operands pre-rounded RNA tf32.
// ---------------------------------------------------------------------------
#define KSTR 68          /* K smem row stride (floats): frag LDS bank-free  */
#define VSTR 72          /* V smem row stride: b-frag LDS bank-free         */
#define PSTR 68          /* Q/P buffer stride                               */
#define OFF_K0 0
#define OFF_K1 (64 * KSTR)                      /* 4352  */
#define OFF_V0 (2 * 64 * KSTR)                  /* 8704  */
#define OFF_V1 (OFF_V0 + 64 * VSTR)             /* 13312 */
#define OFF_QP (OFF_V0 + 2 * 64 * VSTR)         /* 17920 */
#define ATTN_SMEM ((OFF_QP + 128 * PSTR) * 4)   /* 106496 bytes */

__global__ __launch_bounds__(256, 1)
void attn_mma(float* __restrict__ ctx)
{
    extern __shared__ float sh[];
    const uint32_t sb = smem_u32(sh);
    const int tid  = threadIdx.x;
    const int lane = tid & 31, wid = tid >> 5;
    const int g = lane >> 2, t = lane & 3;
    const int qblk = (int)gridDim.x - 1 - (int)blockIdx.x;   // 0..15, long first
    const int bgm  = blockIdx.y;

    const float* Qb = g_q + (size_t)bgm * NSEQ * DH;
    const float* Kb = g_k + (size_t)bgm * NSEQ * DH;
    const float* Vb = g_v + (size_t)bgm * NSEQ * DH;

    const uint32_t koff[2] = { OFF_K0 * 4u, OFF_K1 * 4u };
    const uint32_t voff[2] = { OFF_V0 * 4u, OFF_V1 * 4u };

    const int nkv = 2 * qblk + 2;

    // cp.async K/V tile 0 into buffer 0
    {
#pragma unroll
        for (int i = 0; i < 4; i++) {
            const int idx = tid + i * 256;           // 0..1023
            const int r = idx >> 4, f = idx & 15;    // row 0..63, float4 col
            cp_async16(sb + koff[0] + (r * KSTR + f * 4) * 4, Kb + (size_t)r * DH + f * 4);
            cp_async16(sb + voff[0] + (r * VSTR + f * 4) * 4, Vb + (size_t)r * DH + f * 4);
        }
        cp_commit();
    }

    // load Q tile (128 x 64) into QP buffer, natural layout, stride PSTR
    {
        float* QP = sh + OFF_QP;
#pragma unroll
        for (int i = 0; i < 8; i++) {
            const int idx = tid + i * 256;           // 0..2047
            const int r = idx >> 4, f = idx & 15;
            *(float4*)&QP[r * PSTR + f * 4] =
                *(const float4*)(Qb + (size_t)(qblk * 128 + r) * DH + f * 4);
        }
    }
    __syncthreads();

    // pull Q A-fragments to registers (rows 16*wid .. +15)
    uint32_t qf[8][4];
    {
        const uint32_t* QP = (const uint32_t*)(sh + OFF_QP);
#pragma unroll
        for (int ks = 0; ks < 8; ks++) {
            const uint32_t* p = QP + (16 * wid + g) * PSTR + ks * 8 + t;
            qf[ks][0] = p[0];
            qf[ks][1] = p[8 * PSTR];
            qf[ks][2] = p[4];
            qf[ks][3] = p[8 * PSTR + 4];
        }
    }

    float m_i[2] = { -INFINITY, -INFINITY };
    float l_i[2] = { 0.f, 0.f };
    float Oa[8][4];
#pragma unroll
    for (int nt = 0; nt < 8; nt++)
#pragma unroll
        for (int q = 0; q < 4; q++) Oa[nt][q] = 0.f;

#pragma unroll 1
    for (int jb = 0; jb < nkv; jb++) {
        const int cur = jb & 1;
        cp_wait<0>();          // tile jb resident
        __syncthreads();       // visible to all; prev compute done

        if (jb + 1 < nkv) {    // prefetch tile jb+1 into the other buffer
            const int nxt = (jb + 1) & 1;
            const float* Ksrc = Kb + (size_t)(jb + 1) * 64 * DH;
            const float* Vsrc = Vb + (size_t)(jb + 1) * 64 * DH;
#pragma unroll
            for (int i = 0; i < 4; i++) {
                const int idx = tid + i * 256;
                const int r = idx >> 4, f = idx & 15;
                cp_async16(sb + koff[nxt] + (r * KSTR + f * 4) * 4, Ksrc + (size_t)r * DH + f * 4);
                cp_async16(sb + voff[nxt] + (r * VSTR + f * 4) * 4, Vsrc + (size_t)r * DH + f * 4);
            }
            cp_commit();
        }

        // warps 0..3 are fully masked on the upper diagonal tile: skip
        const bool active = !(jb == 2 * qblk + 1 && wid < 4);
        if (active) {
            // ---- S = Q K^T ----
            float Sa[8][4];
#pragma unroll
            for (int nt = 0; nt < 8; nt++)
#pragma unroll
                for (int q = 0; q < 4; q++) Sa[nt][q] = 0.f;

            const uint32_t* Ksm = (const uint32_t*)(sh + (cur ? OFF_K1 : OFF_K0));
#pragma unroll
            for (int nt = 0; nt < 8; nt++) {
#pragma unroll
                for (int ks = 0; ks < 8; ks++) {
                    uint32_t bf[2];
                    const uint32_t* p = Ksm + (nt * 8 + g) * KSTR + ks * 8 + t;
                    bf[0] = p[0];
                    bf[1] = p[4];
                    mma_tf32(Sa[nt], qf[ks], bf);
                }
            }

            // ---- causal mask (diagonal tiles only) ----
            if (jb >= 2 * qblk) {
                const int colb = jb * 64 + 2 * t;
                const int rowb = qblk * 128 + 16 * wid + g;
#pragma unroll
                for (int nt = 0; nt < 8; nt++) {
                    const int c0 = colb + nt * 8;
                    if (c0 > rowb)     Sa[nt][0] = -INFINITY;
                    if (c0 + 1 > rowb) Sa[nt][1] = -INFINITY;
                    if (c0 > rowb + 8)     Sa[nt][2] = -INFINITY;
                    if (c0 + 1 > rowb + 8) Sa[nt][3] = -INFINITY;
                }
            }

            // ---- online softmax (rows g and g+8; row-mates = 4 lanes) ----
            float* QP = sh + OFF_QP;
#pragma unroll
            for (int h = 0; h < 2; h++) {
                float rmax = -INFINITY;
#pragma unroll
                for (int nt = 0; nt < 8; nt++)
                    rmax = fmaxf(rmax, fmaxf(Sa[nt][2 * h], Sa[nt][2 * h + 1]));
                rmax = fmaxf(rmax, __shfl_xor_sync(0xffffffffu, rmax, 1));
                rmax = fmaxf(rmax, __shfl_xor_sync(0xffffffffu, rmax, 2));
                const float mnew = fmaxf(m_i[h], rmax);
                const float a = __expf(m_i[h] - mnew);
                float rs = 0.f;
#pragma unroll
                for (int nt = 0; nt < 8; nt++) {
                    const float p0 = __expf(Sa[nt][2 * h]     - mnew);
                    const float p1 = __expf(Sa[nt][2 * h + 1] - mnew);
                    Sa[nt][2 * h] = p0; Sa[nt][2 * h + 1] = p1;
                    rs += p0 + p1;
                }
                rs += __shfl_xor_sync(0xffffffffu, rs, 1);
                rs += __shfl_xor_sync(0xffffffffu, rs, 2);
                l_i[h] = l_i[h] * a + rs;
                m_i[h] = mnew;
#pragma unroll
                for (int nt = 0; nt < 8; nt++) {
                    Oa[nt][2 * h] *= a;
                    Oa[nt][2 * h + 1] *= a;
                }
                // store P row (RNA-rounded) to warp-private rows of QP
                const int prow = 16 * wid + g + 8 * h;
#pragma unroll
                for (int nt = 0; nt < 8; nt++) {
                    float2 pv;
                    pv.x = tf32_rna(Sa[nt][2 * h]);
                    pv.y = tf32_rna(Sa[nt][2 * h + 1]);
                    *(float2*)&QP[prow * PSTR + nt * 8 + 2 * t] = pv;
                }
            }
            __syncwarp();

            // ---- O += P V ----
            const uint32_t* Psm = (const uint32_t*)(sh + OFF_QP);
            const uint32_t* Vsm = (const uint32_t*)(sh + (cur ? OFF_V1 : OFF_V0));
#pragma unroll
            for (int ks = 0; ks < 8; ks++) {
                uint32_t pa[4];
                const uint32_t* pp = Psm + (16 * wid + g) * PSTR + ks * 8 + t;
                pa[0] = pp[0];
                pa[1] = pp[8 * PSTR];
                pa[2] = pp[4];
                pa[3] = pp[8 * PSTR + 4];
#pragma unroll
                for (int nt = 0; nt < 8; nt++) {
                    uint32_t bf[2];
                    const uint32_t* vp = Vsm + (ks * 8 + t) * VSTR + nt * 8 + g;
                    bf[0] = vp[0];
                    bf[1] = vp[4 * VSTR];
                    mma_tf32(Oa[nt], pa, bf);
                }
            }
        }
    }

    // ---- epilogue: normalize, write ctx UNSCRAMBLED ----
    const int b_ = bgm >> 4;
    const int gb = (bgm >> 3) & 1;
    const int mp = bgm & 7;
#pragma unroll
    for (int h = 0; h < 2; h++) {
        const float inv = 1.0f / l_i[h];
        const int np = qblk * 128 + 16 * wid + g + 8 * h;
        const int flat = mp * NSEQ + np;
        const int n  = flat >> 3;
        const int mm = flat & 7;
        const int colbase = gb * 512 + mm * 64 + 2 * t;
        float* dst = ctx + (size_t)(b_ * NSEQ + n) * EDIM;
#pragma unroll
        for (int nt = 0; nt < 8; nt++) {
            float2 o;
            o.x = Oa[nt][2 * h] * inv;
            o.y = Oa[nt][2 * h + 1] * inv;
            *(float2*)(dst + colbase + nt * 8) = o;
        }
    }
}

// ---------------------------------------------------------------------------

extern "C" void kernel_launch(void* const* d_in, const int* in_sizes, int n_in,
                              void* d_out, int out_size) {
    (void)in_sizes; (void)n_in; (void)out_size;
    const float* x  = (const float*)d_in[0];
    const float* Wq = (const float*)d_in[1];
    const float* bq = (const float*)d_in[2];
    const float* Wk = (const float*)d_in[3];
    const float* bk = (const float*)d_in[4];
    const float* Wv = (const float*)d_in[5];
    const float* bv = (const float*)d_in[6];
    const float* Wo = (const float*)d_in[7];
    const float* bo = (const float*)d_in[8];
    float* out = (float*)d_out;

    float *pq, *pk, *pv, *pctx;
    cudaGetSymbolAddress((void**)&pq,   g_q);
    cudaGetSymbolAddress((void**)&pk,   g_k);
    cudaGetSymbolAddress((void**)&pv,   g_v);
    cudaGetSymbolAddress((void**)&pctx, g_ctx);

    cudaFuncSetAttribute(gemm_mma<true>,
                         cudaFuncAttributeMaxDynamicSharedMemorySize, GEMM_SMEM);
    cudaFuncSetAttribute(gemm_mma<false>,
                         cudaFuncAttributeMaxDynamicSharedMemorySize, GEMM_SMEM);
    cudaFuncSetAttribute(attn_mma,
                         cudaFuncAttributeMaxDynamicSharedMemorySize, ATTN_SMEM);

    const float scale = 0.125f;  // dh^-0.5, folded into Q (and its bias)

    GemmJobs qkv;
    qkv.j[0] = { Wq, bq, pq, scale };
    qkv.j[1] = { Wk, bk, pk, 1.0f };
    qkv.j[2] = { Wv, bv, pv, 1.0f };
    gemm_mma<true><<<dim3(EDIM / BN, (NBATCH * NSEQ) / BM, 3), 256, GEMM_SMEM>>>(x, qkv);

    attn_mma<<<dim3(NSEQ / 128, NGROUPS), 256, ATTN_SMEM>>>(pctx);

    GemmJobs oj;
    oj.j[0] = { Wo, bo, out, 1.0f };
    oj.j[1] = oj.j[0];
    oj.j[2] = oj.j[0];
    gemm_mma<false><<<dim3(EDIM / BN, (NBATCH * NSEQ) / BM, 1), 256, GEMM_SMEM>>>(pctx, oj);
}

// round 9
// speedup vs baseline: 3.1735x; 1.2809x over previous
#include <cuda_runtime.h>
#include <math.h>
#include <stdint.h>

#define EDIM 1024
#define NSEQ 2048
#define NBATCH 2
#define DH 64
#define NGROUPS 32   /* B * N_BLOCKS * MICRO_HEADS = 2*2*8 */

// Scratch (device globals: no allocation allowed in kernel_launch)
__device__ float g_q[NGROUPS * NSEQ * DH];
__device__ float g_k[NGROUPS * NSEQ * DH];
__device__ float g_v[NGROUPS * NSEQ * DH];
__device__ float g_ctx[NBATCH * NSEQ * EDIM];

// ---------------------------------------------------------------------------
// helpers
// ---------------------------------------------------------------------------
__device__ __forceinline__ float tf32_rna(float x) {
    uint32_t u;
    asm("cvt.rna.tf32.f32 %0, %1;" : "=r"(u) : "f"(x));
    return __uint_as_float(u);
}
__device__ __forceinline__ uint32_t tf32_rna_u(uint32_t x) {
    uint32_t u;
    asm("cvt.rna.tf32.f32 %0, %1;" : "=r"(u) : "f"(__uint_as_float(x)));
    return u;
}

__device__ __forceinline__ void mma_tf32(float* c, const uint32_t* a, const uint32_t* b) {
    asm volatile(
        "mma.sync.aligned.m16n8k8.row.col.f32.tf32.tf32.f32 "
        "{%0,%1,%2,%3}, {%4,%5,%6,%7}, {%8,%9}, {%0,%1,%2,%3};"
        : "+f"(c[0]), "+f"(c[1]), "+f"(c[2]), "+f"(c[3])
        : "r"(a[0]), "r"(a[1]), "r"(a[2]), "r"(a[3]), "r"(b[0]), "r"(b[1]));
}

__device__ __forceinline__ uint32_t smem_u32(const void* p) {
    uint32_t a;
    asm("{ .reg .u64 t; cvta.to.shared.u64 t, %1; cvt.u32.u64 %0, t; }" : "=r"(a) : "l"(p));
    return a;
}

__device__ __forceinline__ void cp_async16(uint32_t dst, const void* src) {
    asm volatile("cp.async.cg.shared.global [%0], [%1], 16;" :: "r"(dst), "l"(src));
}
__device__ __forceinline__ void cp_commit() {
    asm volatile("cp.async.commit_group;" ::: "memory");
}
template<int N>
__device__ __forceinline__ void cp_wait() {
    asm volatile("cp.async.wait_group %0;" :: "n"(N) : "memory");
}

// ---------------------------------------------------------------------------
// tf32 HMMA GEMM v2: occupancy-2, 4-stage cp.async pipeline.
// C[r][c] = alpha * (sum_k A[r][k] * W[c][k] + bias[c])
// A:(rows,1024) W:(1024,1024) row-major K-contiguous (NT GEMM).
// BM=128 BN=128 BK=16, 256 threads, 8 warps (2m x 4n), warp tile 64x32.
// RNA tf32 rounding applied to fragments after LDS (same math as R5).
// ---------------------------------------------------------------------------
#define BM 128
#define BN 128
#define BK 16
#define KST 20                         /* smem row stride: frag LDS bank-free */
#define NKT (EDIM / BK)                /* 64 */
#define NSTG 4
#define STGF ((BM + BN) * KST)         /* 5120 floats = 20 KB per stage */
#define GEMM_SMEM (NSTG * STGF * 4)    /* 81920 bytes */

struct GemmJob  { const float* W; const float* bias; float* C; float alpha; };
struct GemmJobs { GemmJob j[3]; };

template<bool SCRAMBLE>
__global__ __launch_bounds__(256, 2)
void gemm_mma(const float* __restrict__ A, GemmJobs jobs)
{
    const GemmJob job = jobs.j[blockIdx.z];
    const float* __restrict__ W    = job.W;
    const float* __restrict__ bias = job.bias;
    float* __restrict__ C          = job.C;
    const float alpha              = job.alpha;

    extern __shared__ float sh[];
    const uint32_t sb = smem_u32(sh);
    const int tid  = threadIdx.x;
    const int lane = tid & 31, wid = tid >> 5;
    const int g = lane >> 2, t = lane & 3;
    const int wm = (wid >> 2) * 64;          // warp m offset: 0 / 64
    const int wn = (wid & 3) * 32;           // warp n offset: 0/32/64/96
    const int rbase = blockIdx.y * BM;
    const int cbase = blockIdx.x * BN;

    // fill stage s with k-tile kt (4 cp.async per thread; one commit)
    auto fill = [&](int s, int kt) {
        const uint32_t stgA = sb + (uint32_t)(s * STGF) * 4u;
        const uint32_t stgB = stgA + (uint32_t)(BM * KST) * 4u;
#pragma unroll
        for (int j = 0; j < 2; j++) {
            const int idx = tid + j * 256;       // 0..511
            const int r = idx >> 2, f = idx & 3;
            cp_async16(stgA + (uint32_t)(r * KST + f * 4) * 4u,
                       A + (size_t)(rbase + r) * EDIM + kt * BK + f * 4);
        }
#pragma unroll
        for (int j = 0; j < 2; j++) {
            const int idx = tid + j * 256;
            const int r = idx >> 2, f = idx & 3;
            cp_async16(stgB + (uint32_t)(r * KST + f * 4) * 4u,
                       W + (size_t)(cbase + r) * EDIM + kt * BK + f * 4);
        }
        cp_commit();
    };

    // warp tile 64x32 -> mt 0..3 (m16), nt 0..3 (n8): 64 accumulator regs
    float accf[4][4][4];
#pragma unroll
    for (int mt = 0; mt < 4; mt++)
#pragma unroll
        for (int nt = 0; nt < 4; nt++)
#pragma unroll
            for (int q = 0; q < 4; q++) accf[mt][nt][q] = 0.f;

    // prologue: stages 0,1,2
    fill(0, 0);
    fill(1, 1);
    fill(2, 2);

#pragma unroll 1
    for (int kt = 0; kt < NKT; kt++) {
        const int s = kt & (NSTG - 1);
        if (kt < NKT - 2)       cp_wait<2>();
        else if (kt == NKT - 2) cp_wait<1>();
        else                    cp_wait<0>();
        __syncthreads();

        const float* as = sh + s * STGF;
        const float* bs = as + BM * KST;
#pragma unroll
        for (int ks = 0; ks < 2; ks++) {
            uint32_t af[4][4], bf[4][2];
#pragma unroll
            for (int mt = 0; mt < 4; mt++) {
                const uint32_t* p =
                    (const uint32_t*)&as[(wm + mt * 16 + g) * KST + ks * 8 + t];
                af[mt][0] = tf32_rna_u(p[0]);
                af[mt][1] = tf32_rna_u(p[8 * KST]);
                af[mt][2] = tf32_rna_u(p[4]);
                af[mt][3] = tf32_rna_u(p[8 * KST + 4]);
            }
#pragma unroll
            for (int nt = 0; nt < 4; nt++) {
                const uint32_t* p =
                    (const uint32_t*)&bs[(wn + nt * 8 + g) * KST + ks * 8 + t];
                bf[nt][0] = tf32_rna_u(p[0]);
                bf[nt][1] = tf32_rna_u(p[4]);
            }
#pragma unroll
            for (int mt = 0; mt < 4; mt++)
#pragma unroll
                for (int nt = 0; nt < 4; nt++)
                    mma_tf32(accf[mt][nt], af[mt], bf[nt]);
        }

        if (kt + 3 < NKT) fill((kt + 3) & (NSTG - 1), kt + 3);
    }

    // epilogue: c0=(g,2t) c1=(g,2t+1) c2=(g+8,2t) c3=(g+8,2t+1) per fragment
#pragma unroll
    for (int nt = 0; nt < 4; nt++) {
        const int col = cbase + wn + nt * 8 + 2 * t;
        const float2 bb = *(const float2*)&bias[col];
#pragma unroll
        for (int mt = 0; mt < 4; mt++) {
#pragma unroll
            for (int h = 0; h < 2; h++) {
                const int r = rbase + wm + mt * 16 + g + h * 8;
                float2 v;
                v.x = alpha * (accf[mt][nt][h * 2 + 0] + bb.x);
                v.y = alpha * (accf[mt][nt][h * 2 + 1] + bb.y);
                if (SCRAMBLE) {
                    // RNA-round Q/K/V so attention tf32 MMAs see exact operands
                    v.x = tf32_rna(v.x); v.y = tf32_rna(v.y);
                    const int b_ = r >> 11;
                    const int n  = r & (NSEQ - 1);
                    const int gb = col >> 9;
                    const int mm = (col >> 6) & 7;
                    const int dd = col & 63;
                    const int flat = n * 8 + mm;
                    const int mp = flat >> 11;
                    const int np = flat & (NSEQ - 1);
                    *(float2*)(C + ((size_t)((b_ * 2 + gb) * 8 + mp) * NSEQ + np) * DH + dd) = v;
                } else {
                    *(float2*)(C + (size_t)r * EDIM + col) = v;
                }
            }
        }
    }
}

// ---------------------------------------------------------------------------
// Flash attention on tf32 HMMA (unchanged from passing R5 kernel).
// Br=128 (8 warps x m16), Bc=64, dh=64. cp.async double-buffered K/V;
// Q fragments in registers; P smem round-trip (warp-private -> __syncwarp).
// ---------------------------------------------------------------------------
#define KSTR 68
#define VSTR 72
#define PSTR 68
#define OFF_K0 0
#define OFF_K1 (64 * KSTR)
#define OFF_V0 (2 * 64 * KSTR)
#define OFF_V1 (OFF_V0 + 64 * VSTR)
#define OFF_QP (OFF_V0 + 2 * 64 * VSTR)
#define ATTN_SMEM ((OFF_QP + 128 * PSTR) * 4)

__global__ __launch_bounds__(256, 1)
void attn_mma(float* __restrict__ ctx)
{
    extern __shared__ float sh[];
    const uint32_t sb = smem_u32(sh);
    const int tid  = threadIdx.x;
    const int lane = tid & 31, wid = tid >> 5;
    const int g = lane >> 2, t = lane & 3;
    const int qblk = (int)gridDim.x - 1 - (int)blockIdx.x;
    const int bgm  = blockIdx.y;

    const float* Qb = g_q + (size_t)bgm * NSEQ * DH;
    const float* Kb = g_k + (size_t)bgm * NSEQ * DH;
    const float* Vb = g_v + (size_t)bgm * NSEQ * DH;

    const uint32_t koff[2] = { OFF_K0 * 4u, OFF_K1 * 4u };
    const uint32_t voff[2] = { OFF_V0 * 4u, OFF_V1 * 4u };

    const int nkv = 2 * qblk + 2;

    {
#pragma unroll
        for (int i = 0; i < 4; i++) {
            const int idx = tid + i * 256;
            const int r = idx >> 4, f = idx & 15;
            cp_async16(sb + koff[0] + (r * KSTR + f * 4) * 4, Kb + (size_t)r * DH + f * 4);
            cp_async16(sb + voff[0] + (r * VSTR + f * 4) * 4, Vb + (size_t)r * DH + f * 4);
        }
        cp_commit();
    }

    {
        float* QP = sh + OFF_QP;
#pragma unroll
        for (int i = 0; i < 8; i++) {
            const int idx = tid + i * 256;
            const int r = idx >> 4, f = idx & 15;
            *(float4*)&QP[r * PSTR + f * 4] =
                *(const float4*)(Qb + (size_t)(qblk * 128 + r) * DH + f * 4);
        }
    }
    __syncthreads();

    uint32_t qf[8][4];
    {
        const uint32_t* QP = (const uint32_t*)(sh + OFF_QP);
#pragma unroll
        for (int ks = 0; ks < 8; ks++) {
            const uint32_t* p = QP + (16 * wid + g) * PSTR + ks * 8 + t;
            qf[ks][0] = p[0];
            qf[ks][1] = p[8 * PSTR];
            qf[ks][2] = p[4];
            qf[ks][3] = p[8 * PSTR + 4];
        }
    }

    float m_i[2] = { -INFINITY, -INFINITY };
    float l_i[2] = { 0.f, 0.f };
    float Oa[8][4];
#pragma unroll
    for (int nt = 0; nt < 8; nt++)
#pragma unroll
        for (int q = 0; q < 4; q++) Oa[nt][q] = 0.f;

#pragma unroll 1
    for (int jb = 0; jb < nkv; jb++) {
        const int cur = jb & 1;
        cp_wait<0>();
        __syncthreads();

        if (jb + 1 < nkv) {
            const int nxt = (jb + 1) & 1;
            const float* Ksrc = Kb + (size_t)(jb + 1) * 64 * DH;
            const float* Vsrc = Vb + (size_t)(jb + 1) * 64 * DH;
#pragma unroll
            for (int i = 0; i < 4; i++) {
                const int idx = tid + i * 256;
                const int r = idx >> 4, f = idx & 15;
                cp_async16(sb + koff[nxt] + (r * KSTR + f * 4) * 4, Ksrc + (size_t)r * DH + f * 4);
                cp_async16(sb + voff[nxt] + (r * VSTR + f * 4) * 4, Vsrc + (size_t)r * DH + f * 4);
            }
            cp_commit();
        }

        const bool active = !(jb == 2 * qblk + 1 && wid < 4);
        if (active) {
            float Sa[8][4];
#pragma unroll
            for (int nt = 0; nt < 8; nt++)
#pragma unroll
                for (int q = 0; q < 4; q++) Sa[nt][q] = 0.f;

            const uint32_t* Ksm = (const uint32_t*)(sh + (cur ? OFF_K1 : OFF_K0));
#pragma unroll
            for (int nt = 0; nt < 8; nt++) {
#pragma unroll
                for (int ks = 0; ks < 8; ks++) {
                    uint32_t bf[2];
                    const uint32_t* p = Ksm + (nt * 8 + g) * KSTR + ks * 8 + t;
                    bf[0] = p[0];
                    bf[1] = p[4];
                    mma_tf32(Sa[nt], qf[ks], bf);
                }
            }

            if (jb >= 2 * qblk) {
                const int colb = jb * 64 + 2 * t;
                const int rowb = qblk * 128 + 16 * wid + g;
#pragma unroll
                for (int nt = 0; nt < 8; nt++) {
                    const int c0 = colb + nt * 8;
                    if (c0 > rowb)     Sa[nt][0] = -INFINITY;
                    if (c0 + 1 > rowb) Sa[nt][1] = -INFINITY;
                    if (c0 > rowb + 8)     Sa[nt][2] = -INFINITY;
                    if (c0 + 1 > rowb + 8) Sa[nt][3] = -INFINITY;
                }
            }

            float* QP = sh + OFF_QP;
#pragma unroll
            for (int h = 0; h < 2; h++) {
                float rmax = -INFINITY;
#pragma unroll
                for (int nt = 0; nt < 8; nt++)
                    rmax = fmaxf(rmax, fmaxf(Sa[nt][2 * h], Sa[nt][2 * h + 1]));
                rmax = fmaxf(rmax, __shfl_xor_sync(0xffffffffu, rmax, 1));
                rmax = fmaxf(rmax, __shfl_xor_sync(0xffffffffu, rmax, 2));
                const float mnew = fmaxf(m_i[h], rmax);
                const float a = __expf(m_i[h] - mnew);
                float rs = 0.f;
#pragma unroll
                for (int nt = 0; nt < 8; nt++) {
                    const float p0 = __expf(Sa[nt][2 * h]     - mnew);
                    const float p1 = __expf(Sa[nt][2 * h + 1] - mnew);
                    Sa[nt][2 * h] = p0; Sa[nt][2 * h + 1] = p1;
                    rs += p0 + p1;
                }
                rs += __shfl_xor_sync(0xffffffffu, rs, 1);
                rs += __shfl_xor_sync(0xffffffffu, rs, 2);
                l_i[h] = l_i[h] * a + rs;
                m_i[h] = mnew;
#pragma unroll
                for (int nt = 0; nt < 8; nt++) {
                    Oa[nt][2 * h] *= a;
                    Oa[nt][2 * h + 1] *= a;
                }
                const int prow = 16 * wid + g + 8 * h;
#pragma unroll
                for (int nt = 0; nt < 8; nt++) {
                    float2 pv;
                    pv.x = tf32_rna(Sa[nt][2 * h]);
                    pv.y = tf32_rna(Sa[nt][2 * h + 1]);
                    *(float2*)&QP[prow * PSTR + nt * 8 + 2 * t] = pv;
                }
            }
            __syncwarp();

            const uint32_t* Psm = (const uint32_t*)(sh + OFF_QP);
            const uint32_t* Vsm = (const uint32_t*)(sh + (cur ? OFF_V1 : OFF_V0));
#pragma unroll
            for (int ks = 0; ks < 8; ks++) {
                uint32_t pa[4];
                const uint32_t* pp = Psm + (16 * wid + g) * PSTR + ks * 8 + t;
                pa[0] = pp[0];
                pa[1] = pp[8 * PSTR];
                pa[2] = pp[4];
                pa[3] = pp[8 * PSTR + 4];
#pragma unroll
                for (int nt = 0; nt < 8; nt++) {
                    uint32_t bf[2];
                    const uint32_t* vp = Vsm + (ks * 8 + t) * VSTR + nt * 8 + g;
                    bf[0] = vp[0];
                    bf[1] = vp[4 * VSTR];
                    mma_tf32(Oa[nt], pa, bf);
                }
            }
        }
    }

    const int b_ = bgm >> 4;
    const int gb = (bgm >> 3) & 1;
    const int mp = bgm & 7;
#pragma unroll
    for (int h = 0; h < 2; h++) {
        const float inv = 1.0f / l_i[h];
        const int np = qblk * 128 + 16 * wid + g + 8 * h;
        const int flat = mp * NSEQ + np;
        const int n  = flat >> 3;
        const int mm = flat & 7;
        const int colbase = gb * 512 + mm * 64 + 2 * t;
        float* dst = ctx + (size_t)(b_ * NSEQ + n) * EDIM;
#pragma unroll
        for (int nt = 0; nt < 8; nt++) {
            float2 o;
            o.x = Oa[nt][2 * h] * inv;
            o.y = Oa[nt][2 * h + 1] * inv;
            *(float2*)(dst + colbase + nt * 8) = o;
        }
    }
}

// ---------------------------------------------------------------------------

extern "C" void kernel_launch(void* const* d_in, const int* in_sizes, int n_in,
                              void* d_out, int out_size) {
    (void)in_sizes; (void)n_in; (void)out_size;
    const float* x  = (const float*)d_in[0];
    const float* Wq = (const float*)d_in[1];
    const float* bq = (const float*)d_in[2];
    const float* Wk = (const float*)d_in[3];
    const float* bk = (const float*)d_in[4];
    const float* Wv = (const float*)d_in[5];
    const float* bv = (const float*)d_in[6];
    const float* Wo = (const float*)d_in[7];
    const float* bo = (const float*)d_in[8];
    float* out = (float*)d_out;

    float *pq, *pk, *pv, *pctx;
    cudaGetSymbolAddress((void**)&pq,   g_q);
    cudaGetSymbolAddress((void**)&pk,   g_k);
    cudaGetSymbolAddress((void**)&pv,   g_v);
    cudaGetSymbolAddress((void**)&pctx, g_ctx);

    cudaFuncSetAttribute(gemm_mma<true>,
                         cudaFuncAttributeMaxDynamicSharedMemorySize, GEMM_SMEM);
    cudaFuncSetAttribute(gemm_mma<false>,
                         cudaFuncAttributeMaxDynamicSharedMemorySize, GEMM_SMEM);
    cudaFuncSetAttribute(attn_mma,
                         cudaFuncAttributeMaxDynamicSharedMemorySize, ATTN_SMEM);

    const float scale = 0.125f;  // dh^-0.5, folded into Q (and its bias)

    GemmJobs qkv;
    qkv.j[0] = { Wq, bq, pq, scale };
    qkv.j[1] = { Wk, bk, pk, 1.0f };
    qkv.j[2] = { Wv, bv, pv, 1.0f };
    gemm_mma<true><<<dim3(EDIM / BN, (NBATCH * NSEQ) / BM, 3), 256, GEMM_SMEM>>>(x, qkv);

    attn_mma<<<dim3(NSEQ / 128, NGROUPS), 256, ATTN_SMEM>>>(pctx);

    GemmJobs oj;
    oj.j[0] = { Wo, bo, out, 1.0f };
    oj.j[1] = oj.j[0];
    oj.j[2] = oj.j[0];
    gemm_mma<false><<<dim3(EDIM / BN, (NBATCH * NSEQ) / BM, 1), 256, GEMM_SMEM>>>(pctx, oj);
}

// round 10
// speedup vs baseline: 3.2266x; 1.0167x over previous
#include <cuda_runtime.h>
#include <math.h>
#include <stdint.h>

#define EDIM 1024
#define NSEQ 2048
#define NBATCH 2
#define DH 64
#define NGROUPS 32   /* B * N_BLOCKS * MICRO_HEADS = 2*2*8 */

// Scratch (device globals: no allocation allowed in kernel_launch)
__device__ float g_q[NGROUPS * NSEQ * DH];
__device__ float g_k[NGROUPS * NSEQ * DH];
__device__ float g_v[NGROUPS * NSEQ * DH];
__device__ float g_ctx[NBATCH * NSEQ * EDIM];
__device__ float g_xr[NBATCH * NSEQ * EDIM];   // RNA-rounded x
__device__ float g_wr[4 * EDIM * EDIM];        // RNA-rounded Wq,Wk,Wv,Wo

// ---------------------------------------------------------------------------
// helpers
// ---------------------------------------------------------------------------
__device__ __forceinline__ float tf32_rna(float x) {
    uint32_t u;
    asm("cvt.rna.tf32.f32 %0, %1;" : "=r"(u) : "f"(x));
    return __uint_as_float(u);
}

__device__ __forceinline__ void mma_tf32(float* c, const uint32_t* a, const uint32_t* b) {
    asm volatile(
        "mma.sync.aligned.m16n8k8.row.col.f32.tf32.tf32.f32 "
        "{%0,%1,%2,%3}, {%4,%5,%6,%7}, {%8,%9}, {%0,%1,%2,%3};"
        : "+f"(c[0]), "+f"(c[1]), "+f"(c[2]), "+f"(c[3])
        : "r"(a[0]), "r"(a[1]), "r"(a[2]), "r"(a[3]), "r"(b[0]), "r"(b[1]));
}

__device__ __forceinline__ uint32_t smem_u32(const void* p) {
    uint32_t a;
    asm("{ .reg .u64 t; cvta.to.shared.u64 t, %1; cvt.u32.u64 %0, t; }" : "=r"(a) : "l"(p));
    return a;
}

__device__ __forceinline__ void cp_async16(uint32_t dst, const void* src) {
    asm volatile("cp.async.cg.shared.global [%0], [%1], 16;" :: "r"(dst), "l"(src));
}
__device__ __forceinline__ void cp_commit() {
    asm volatile("cp.async.commit_group;" ::: "memory");
}
template<int N>
__device__ __forceinline__ void cp_wait() {
    asm volatile("cp.async.wait_group %0;" :: "n"(N) : "memory");
}

// ---------------------------------------------------------------------------
// Pre-round pass: RNA-round x and all W's into scratch (hoists all inner-loop
// cvts out of the GEMMs; values bit-identical to R8's fragment-side rounding).
// ---------------------------------------------------------------------------
#define XF4 (NBATCH * NSEQ * EDIM / 4)   /* 1048576 */
#define WF4 (EDIM * EDIM / 4)            /*  262144 */
#define TOTF4 (XF4 + 4 * WF4)

__global__ __launch_bounds__(256)
void prernd(const float4* __restrict__ x,
            const float4* __restrict__ wq, const float4* __restrict__ wk,
            const float4* __restrict__ wv, const float4* __restrict__ wo,
            float4* __restrict__ xr, float4* __restrict__ wr)
{
    for (int i = blockIdx.x * blockDim.x + threadIdx.x; i < TOTF4;
         i += gridDim.x * blockDim.x) {
        const float4* src;
        float4* dst;
        if (i < XF4) {
            src = x + i; dst = xr + i;
        } else {
            const int j = i - XF4;
            const int w = j / WF4, o = j - w * WF4;
            const float4* ws = (w == 0) ? wq : (w == 1) ? wk : (w == 2) ? wv : wo;
            src = ws + o; dst = wr + j;
        }
        float4 v = *src;
        v.x = tf32_rna(v.x); v.y = tf32_rna(v.y);
        v.z = tf32_rna(v.z); v.w = tf32_rna(v.w);
        *dst = v;
    }
}

// ---------------------------------------------------------------------------
// tf32 HMMA GEMM v3: occupancy-2, 4-stage cp.async pipeline, pre-rounded
// inputs (no cvts in the mainloop).
// C[r][c] = alpha * (sum_k A[r][k] * W[c][k] + bias[c])
// BM=128 BN=128 BK=16, 256 threads, 8 warps (2m x 4n), warp tile 64x32.
// ---------------------------------------------------------------------------
#define BM 128
#define BN 128
#define BK 16
#define KST 20                         /* smem row stride: frag LDS bank-free */
#define NKT (EDIM / BK)                /* 64 */
#define NSTG 4
#define STGF ((BM + BN) * KST)         /* 5120 floats = 20 KB per stage */
#define GEMM_SMEM (NSTG * STGF * 4)    /* 81920 bytes */

struct GemmJob  { const float* W; const float* bias; float* C; float alpha; };
struct GemmJobs { GemmJob j[3]; };

template<bool SCRAMBLE>
__global__ __launch_bounds__(256, 2)
void gemm_mma(const float* __restrict__ A, GemmJobs jobs)
{
    const GemmJob job = jobs.j[blockIdx.z];
    const float* __restrict__ W    = job.W;
    const float* __restrict__ bias = job.bias;
    float* __restrict__ C          = job.C;
    const float alpha              = job.alpha;

    extern __shared__ float sh[];
    const uint32_t sb = smem_u32(sh);
    const int tid  = threadIdx.x;
    const int lane = tid & 31, wid = tid >> 5;
    const int g = lane >> 2, t = lane & 3;
    const int wm = (wid >> 2) * 64;          // warp m offset: 0 / 64
    const int wn = (wid & 3) * 32;           // warp n offset: 0/32/64/96
    const int rbase = blockIdx.y * BM;
    const int cbase = blockIdx.x * BN;

    auto fill = [&](int s, int kt) {
        const uint32_t stgA = sb + (uint32_t)(s * STGF) * 4u;
        const uint32_t stgB = stgA + (uint32_t)(BM * KST) * 4u;
#pragma unroll
        for (int j = 0; j < 2; j++) {
            const int idx = tid + j * 256;
            const int r = idx >> 2, f = idx & 3;
            cp_async16(stgA + (uint32_t)(r * KST + f * 4) * 4u,
                       A + (size_t)(rbase + r) * EDIM + kt * BK + f * 4);
        }
#pragma unroll
        for (int j = 0; j < 2; j++) {
            const int idx = tid + j * 256;
            const int r = idx >> 2, f = idx & 3;
            cp_async16(stgB + (uint32_t)(r * KST + f * 4) * 4u,
                       W + (size_t)(cbase + r) * EDIM + kt * BK + f * 4);
        }
        cp_commit();
    };

    float accf[4][4][4];
#pragma unroll
    for (int mt = 0; mt < 4; mt++)
#pragma unroll
        for (int nt = 0; nt < 4; nt++)
#pragma unroll
            for (int q = 0; q < 4; q++) accf[mt][nt][q] = 0.f;

    fill(0, 0);
    fill(1, 1);
    fill(2, 2);

#pragma unroll 1
    for (int kt = 0; kt < NKT; kt++) {
        const int s = kt & (NSTG - 1);
        if (kt < NKT - 2)       cp_wait<2>();
        else if (kt == NKT - 2) cp_wait<1>();
        else                    cp_wait<0>();
        __syncthreads();

        const float* as = sh + s * STGF;
        const float* bs = as + BM * KST;
#pragma unroll
        for (int ks = 0; ks < 2; ks++) {
            uint32_t af[4][4], bf[4][2];
#pragma unroll
            for (int mt = 0; mt < 4; mt++) {
                const uint32_t* p =
                    (const uint32_t*)&as[(wm + mt * 16 + g) * KST + ks * 8 + t];
                af[mt][0] = p[0];
                af[mt][1] = p[8 * KST];
                af[mt][2] = p[4];
                af[mt][3] = p[8 * KST + 4];
            }
#pragma unroll
            for (int nt = 0; nt < 4; nt++) {
                const uint32_t* p =
                    (const uint32_t*)&bs[(wn + nt * 8 + g) * KST + ks * 8 + t];
                bf[nt][0] = p[0];
                bf[nt][1] = p[4];
            }
#pragma unroll
            for (int mt = 0; mt < 4; mt++)
#pragma unroll
                for (int nt = 0; nt < 4; nt++)
                    mma_tf32(accf[mt][nt], af[mt], bf[nt]);
        }

        if (kt + 3 < NKT) fill((kt + 3) & (NSTG - 1), kt + 3);
    }

    // epilogue: c0=(g,2t) c1=(g,2t+1) c2=(g+8,2t) c3=(g+8,2t+1) per fragment
#pragma unroll
    for (int nt = 0; nt < 4; nt++) {
        const int col = cbase + wn + nt * 8 + 2 * t;
        const float2 bb = *(const float2*)&bias[col];
#pragma unroll
        for (int mt = 0; mt < 4; mt++) {
#pragma unroll
            for (int h = 0; h < 2; h++) {
                const int r = rbase + wm + mt * 16 + g + h * 8;
                float2 v;
                v.x = alpha * (accf[mt][nt][h * 2 + 0] + bb.x);
                v.y = alpha * (accf[mt][nt][h * 2 + 1] + bb.y);
                if (SCRAMBLE) {
                    // RNA-round Q/K/V so attention tf32 MMAs see exact operands
                    v.x = tf32_rna(v.x); v.y = tf32_rna(v.y);
                    const int b_ = r >> 11;
                    const int n  = r & (NSEQ - 1);
                    const int gb = col >> 9;
                    const int mm = (col >> 6) & 7;
                    const int dd = col & 63;
                    const int flat = n * 8 + mm;
                    const int mp = flat >> 11;
                    const int np = flat & (NSEQ - 1);
                    *(float2*)(C + ((size_t)((b_ * 2 + gb) * 8 + mp) * NSEQ + np) * DH + dd) = v;
                } else {
                    *(float2*)(C + (size_t)r * EDIM + col) = v;
                }
            }
        }
    }
}

// ---------------------------------------------------------------------------
// Flash attention on tf32 HMMA. Same structure as passing R8 kernel, with:
//  - __launch_bounds__(256, 2): 2 CTAs/SM (smem 104 KB x 2 fits in 228 KB)
//  - epilogue RNA-rounds ctx (feeds the O-GEMM, whose fragment cvts are gone)
// ---------------------------------------------------------------------------
#define KSTR 68
#define VSTR 72
#define PSTR 68
#define OFF_K0 0
#define OFF_K1 (64 * KSTR)
#define OFF_V0 (2 * 64 * KSTR)
#define OFF_V1 (OFF_V0 + 64 * VSTR)
#define OFF_QP (OFF_V0 + 2 * 64 * VSTR)
#define ATTN_SMEM ((OFF_QP + 128 * PSTR) * 4)

__global__ __launch_bounds__(256, 2)
void attn_mma(float* __restrict__ ctx)
{
    extern __shared__ float sh[];
    const uint32_t sb = smem_u32(sh);
    const int tid  = threadIdx.x;
    const int lane = tid & 31, wid = tid >> 5;
    const int g = lane >> 2, t = lane & 3;
    const int qblk = (int)gridDim.x - 1 - (int)blockIdx.x;
    const int bgm  = blockIdx.y;

    const float* Qb = g_q + (size_t)bgm * NSEQ * DH;
    const float* Kb = g_k + (size_t)bgm * NSEQ * DH;
    const float* Vb = g_v + (size_t)bgm * NSEQ * DH;

    const uint32_t koff[2] = { OFF_K0 * 4u, OFF_K1 * 4u };
    const uint32_t voff[2] = { OFF_V0 * 4u, OFF_V1 * 4u };

    const int nkv = 2 * qblk + 2;

    {
#pragma unroll
        for (int i = 0; i < 4; i++) {
            const int idx = tid + i * 256;
            const int r = idx >> 4, f = idx & 15;
            cp_async16(sb + koff[0] + (r * KSTR + f * 4) * 4, Kb + (size_t)r * DH + f * 4);
            cp_async16(sb + voff[0] + (r * VSTR + f * 4) * 4, Vb + (size_t)r * DH + f * 4);
        }
        cp_commit();
    }

    {
        float* QP = sh + OFF_QP;
#pragma unroll
        for (int i = 0; i < 8; i++) {
            const int idx = tid + i * 256;
            const int r = idx >> 4, f = idx & 15;
            *(float4*)&QP[r * PSTR + f * 4] =
                *(const float4*)(Qb + (size_t)(qblk * 128 + r) * DH + f * 4);
        }
    }
    __syncthreads();

    uint32_t qf[8][4];
    {
        const uint32_t* QP = (const uint32_t*)(sh + OFF_QP);
#pragma unroll
        for (int ks = 0; ks < 8; ks++) {
            const uint32_t* p = QP + (16 * wid + g) * PSTR + ks * 8 + t;
            qf[ks][0] = p[0];
            qf[ks][1] = p[8 * PSTR];
            qf[ks][2] = p[4];
            qf[ks][3] = p[8 * PSTR + 4];
        }
    }

    float m_i[2] = { -INFINITY, -INFINITY };
    float l_i[2] = { 0.f, 0.f };
    float Oa[8][4];
#pragma unroll
    for (int nt = 0; nt < 8; nt++)
#pragma unroll
        for (int q = 0; q < 4; q++) Oa[nt][q] = 0.f;

#pragma unroll 1
    for (int jb = 0; jb < nkv; jb++) {
        const int cur = jb & 1;
        cp_wait<0>();
        __syncthreads();

        if (jb + 1 < nkv) {
            const int nxt = (jb + 1) & 1;
            const float* Ksrc = Kb + (size_t)(jb + 1) * 64 * DH;
            const float* Vsrc = Vb + (size_t)(jb + 1) * 64 * DH;
#pragma unroll
            for (int i = 0; i < 4; i++) {
                const int idx = tid + i * 256;
                const int r = idx >> 4, f = idx & 15;
                cp_async16(sb + koff[nxt] + (r * KSTR + f * 4) * 4, Ksrc + (size_t)r * DH + f * 4);
                cp_async16(sb + voff[nxt] + (r * VSTR + f * 4) * 4, Vsrc + (size_t)r * DH + f * 4);
            }
            cp_commit();
        }

        const bool active = !(jb == 2 * qblk + 1 && wid < 4);
        if (active) {
            float Sa[8][4];
#pragma unroll
            for (int nt = 0; nt < 8; nt++)
#pragma unroll
                for (int q = 0; q < 4; q++) Sa[nt][q] = 0.f;

            const uint32_t* Ksm = (const uint32_t*)(sh + (cur ? OFF_K1 : OFF_K0));
#pragma unroll
            for (int nt = 0; nt < 8; nt++) {
#pragma unroll
                for (int ks = 0; ks < 8; ks++) {
                    uint32_t bf[2];
                    const uint32_t* p = Ksm + (nt * 8 + g) * KSTR + ks * 8 + t;
                    bf[0] = p[0];
                    bf[1] = p[4];
                    mma_tf32(Sa[nt], qf[ks], bf);
                }
            }

            if (jb >= 2 * qblk) {
                const int colb = jb * 64 + 2 * t;
                const int rowb = qblk * 128 + 16 * wid + g;
#pragma unroll
                for (int nt = 0; nt < 8; nt++) {
                    const int c0 = colb + nt * 8;
                    if (c0 > rowb)     Sa[nt][0] = -INFINITY;
                    if (c0 + 1 > rowb) Sa[nt][1] = -INFINITY;
                    if (c0 > rowb + 8)     Sa[nt][2] = -INFINITY;
                    if (c0 + 1 > rowb + 8) Sa[nt][3] = -INFINITY;
                }
            }

            float* QP = sh + OFF_QP;
#pragma unroll
            for (int h = 0; h < 2; h++) {
                float rmax = -INFINITY;
#pragma unroll
                for (int nt = 0; nt < 8; nt++)
                    rmax = fmaxf(rmax, fmaxf(Sa[nt][2 * h], Sa[nt][2 * h + 1]));
                rmax = fmaxf(rmax, __shfl_xor_sync(0xffffffffu, rmax, 1));
                rmax = fmaxf(rmax, __shfl_xor_sync(0xffffffffu, rmax, 2));
                const float mnew = fmaxf(m_i[h], rmax);
                const float a = __expf(m_i[h] - mnew);
                float rs = 0.f;
#pragma unroll
                for (int nt = 0; nt < 8; nt++) {
                    const float p0 = __expf(Sa[nt][2 * h]     - mnew);
                    const float p1 = __expf(Sa[nt][2 * h + 1] - mnew);
                    Sa[nt][2 * h] = p0; Sa[nt][2 * h + 1] = p1;
                    rs += p0 + p1;
                }
                rs += __shfl_xor_sync(0xffffffffu, rs, 1);
                rs += __shfl_xor_sync(0xffffffffu, rs, 2);
                l_i[h] = l_i[h] * a + rs;
                m_i[h] = mnew;
#pragma unroll
                for (int nt = 0; nt < 8; nt++) {
                    Oa[nt][2 * h] *= a;
                    Oa[nt][2 * h + 1] *= a;
                }
                const int prow = 16 * wid + g + 8 * h;
#pragma unroll
                for (int nt = 0; nt < 8; nt++) {
                    float2 pv;
                    pv.x = tf32_rna(Sa[nt][2 * h]);
                    pv.y = tf32_rna(Sa[nt][2 * h + 1]);
                    *(float2*)&QP[prow * PSTR + nt * 8 + 2 * t] = pv;
                }
            }
            __syncwarp();

            const uint32_t* Psm = (const uint32_t*)(sh + OFF_QP);
            const uint32_t* Vsm = (const uint32_t*)(sh + (cur ? OFF_V1 : OFF_V0));
#pragma unroll
            for (int ks = 0; ks < 8; ks++) {
                uint32_t pa[4];
                const uint32_t* pp = Psm + (16 * wid + g) * PSTR + ks * 8 + t;
                pa[0] = pp[0];
                pa[1] = pp[8 * PSTR];
                pa[2] = pp[4];
                pa[3] = pp[8 * PSTR + 4];
#pragma unroll
                for (int nt = 0; nt < 8; nt++) {
                    uint32_t bf[2];
                    const uint32_t* vp = Vsm + (ks * 8 + t) * VSTR + nt * 8 + g;
                    bf[0] = vp[0];
                    bf[1] = vp[4 * VSTR];
                    mma_tf32(Oa[nt], pa, bf);
                }
            }
        }
    }

    // epilogue: normalize, RNA-round (feeds O-GEMM), write ctx UNSCRAMBLED
    const int b_ = bgm >> 4;
    const int gb = (bgm >> 3) & 1;
    const int mp = bgm & 7;
#pragma unroll
    for (int h = 0; h < 2; h++) {
        const float inv = 1.0f / l_i[h];
        const int np = qblk * 128 + 16 * wid + g + 8 * h;
        const int flat = mp * NSEQ + np;
        const int n  = flat >> 3;
        const int mm = flat & 7;
        const int colbase = gb * 512 + mm * 64 + 2 * t;
        float* dst = ctx + (size_t)(b_ * NSEQ + n) * EDIM;
#pragma unroll
        for (int nt = 0; nt < 8; nt++) {
            float2 o;
            o.x = tf32_rna(Oa[nt][2 * h] * inv);
            o.y = tf32_rna(Oa[nt][2 * h + 1] * inv);
            *(float2*)(dst + colbase + nt * 8) = o;
        }
    }
}

// ---------------------------------------------------------------------------

extern "C" void kernel_launch(void* const* d_in, const int* in_sizes, int n_in,
                              void* d_out, int out_size) {
    (void)in_sizes; (void)n_in; (void)out_size;
    const float* x  = (const float*)d_in[0];
    const float* Wq = (const float*)d_in[1];
    const float* bq = (const float*)d_in[2];
    const float* Wk = (const float*)d_in[3];
    const float* bk = (const float*)d_in[4];
    const float* Wv = (const float*)d_in[5];
    const float* bv = (const float*)d_in[6];
    const float* Wo = (const float*)d_in[7];
    const float* bo = (const float*)d_in[8];
    float* out = (float*)d_out;

    float *pq, *pk, *pv, *pctx, *pxr, *pwr;
    cudaGetSymbolAddress((void**)&pq,   g_q);
    cudaGetSymbolAddress((void**)&pk,   g_k);
    cudaGetSymbolAddress((void**)&pv,   g_v);
    cudaGetSymbolAddress((void**)&pctx, g_ctx);
    cudaGetSymbolAddress((void**)&pxr,  g_xr);
    cudaGetSymbolAddress((void**)&pwr,  g_wr);

    cudaFuncSetAttribute(gemm_mma<true>,
                         cudaFuncAttributeMaxDynamicSharedMemorySize, GEMM_SMEM);
    cudaFuncSetAttribute(gemm_mma<false>,
                         cudaFuncAttributeMaxDynamicSharedMemorySize, GEMM_SMEM);
    cudaFuncSetAttribute(attn_mma,
                         cudaFuncAttributeMaxDynamicSharedMemorySize, ATTN_SMEM);

    // 1) pre-round x and all W's into scratch
    prernd<<<2048, 256>>>((const float4*)x,
                          (const float4*)Wq, (const float4*)Wk,
                          (const float4*)Wv, (const float4*)Wo,
                          (float4*)pxr, (float4*)pwr);

    const float scale = 0.125f;  // dh^-0.5, folded into Q (and its bias)
    const float* wr = pwr;

    // 2) QKV projections (fused z-grid)
    GemmJobs qkv;
    qkv.j[0] = { wr + 0 * (size_t)EDIM * EDIM, bq, pq, scale };
    qkv.j[1] = { wr + 1 * (size_t)EDIM * EDIM, bk, pk, 1.0f };
    qkv.j[2] = { wr + 2 * (size_t)EDIM * EDIM, bv, pv, 1.0f };
    gemm_mma<true><<<dim3(EDIM / BN, (NBATCH * NSEQ) / BM, 3), 256, GEMM_SMEM>>>(pxr, qkv);

    // 3) attention
    attn_mma<<<dim3(NSEQ / 128, NGROUPS), 256, ATTN_SMEM>>>(pctx);

    // 4) output projection
    GemmJobs oj;
    oj.j[0] = { wr + 3 * (size_t)EDIM * EDIM, bo, out, 1.0f };
    oj.j[1] = oj.j[0];
    oj.j[2] = oj.j[0];
    gemm_mma<false><<<dim3(EDIM / BN, (NBATCH * NSEQ) / BM, 1), 256, GEMM_SMEM>>>(pctx, oj);
}

// round 11
// speedup vs baseline: 5.3982x; 1.6730x over previous
#include <cuda_runtime.h>
#include <cuda_fp16.h>
#include <math.h>
#include <stdint.h>

#define EDIM 1024
#define NSEQ 2048
#define NBATCH 2
#define DH 64
#define NGROUPS 32   /* B * N_BLOCKS * MICRO_HEADS = 2*2*8 */

// Scratch (device globals: no allocation allowed in kernel_launch)
__device__ __half g_q[NGROUPS * NSEQ * DH];
__device__ __half g_k[NGROUPS * NSEQ * DH];
__device__ __half g_v[NGROUPS * NSEQ * DH];
__device__ __half g_ctx[NBATCH * NSEQ * EDIM];
__device__ __half g_xh[NBATCH * NSEQ * EDIM];   // fp16 x
__device__ __half g_wh[4 * EDIM * EDIM];        // fp16 Wq,Wk,Wv,Wo

// ---------------------------------------------------------------------------
// helpers
// ---------------------------------------------------------------------------
__device__ __forceinline__ void mma_f16(float* c, const uint32_t* a, const uint32_t* b) {
    asm volatile(
        "mma.sync.aligned.m16n8k16.row.col.f32.f16.f16.f32 "
        "{%0,%1,%2,%3}, {%4,%5,%6,%7}, {%8,%9}, {%0,%1,%2,%3};"
        : "+f"(c[0]), "+f"(c[1]), "+f"(c[2]), "+f"(c[3])
        : "r"(a[0]), "r"(a[1]), "r"(a[2]), "r"(a[3]), "r"(b[0]), "r"(b[1]));
}

__device__ __forceinline__ uint32_t smem_u32(const void* p) {
    uint32_t a;
    asm("{ .reg .u64 t; cvta.to.shared.u64 t, %1; cvt.u32.u64 %0, t; }" : "=r"(a) : "l"(p));
    return a;
}

__device__ __forceinline__ void cp_async16(uint32_t dst, const void* src) {
    asm volatile("cp.async.cg.shared.global [%0], [%1], 16;" :: "r"(dst), "l"(src));
}
__device__ __forceinline__ void cp_commit() {
    asm volatile("cp.async.commit_group;" ::: "memory");
}
template<int N>
__device__ __forceinline__ void cp_wait() {
    asm volatile("cp.async.wait_group %0;" :: "n"(N) : "memory");
}

// ---------------------------------------------------------------------------
// Pre-convert pass: x and all W's -> fp16 (RN). fp16 mantissa == tf32
// mantissa, so per-element quantization error matches the tf32 path.
// ---------------------------------------------------------------------------
#define XF4 (NBATCH * NSEQ * EDIM / 4)   /* 1048576 */
#define WF4 (EDIM * EDIM / 4)            /*  262144 */
#define TOTF4 (XF4 + 4 * WF4)

__global__ __launch_bounds__(256)
void precvt(const float4* __restrict__ x,
            const float4* __restrict__ wq, const float4* __restrict__ wk,
            const float4* __restrict__ wv, const float4* __restrict__ wo,
            uint2* __restrict__ xh, uint2* __restrict__ wh)
{
    for (int i = blockIdx.x * blockDim.x + threadIdx.x; i < TOTF4;
         i += gridDim.x * blockDim.x) {
        const float4* src;
        uint2* dst;
        if (i < XF4) {
            src = x + i; dst = xh + i;
        } else {
            const int j = i - XF4;
            const int w = j / WF4, o = j - w * WF4;
            const float4* ws = (w == 0) ? wq : (w == 1) ? wk : (w == 2) ? wv : wo;
            src = ws + o; dst = wh + j;
        }
        float4 v = *src;
        union { __half2 h2[2]; uint2 u; } cv;
        cv.h2[0] = __floats2half2_rn(v.x, v.y);
        cv.h2[1] = __floats2half2_rn(v.z, v.w);
        *dst = cv.u;
    }
}

// ---------------------------------------------------------------------------
// fp16 HMMA GEMM: occupancy-2, 4-stage cp.async pipeline, m16n8k16.
// C[r][c] = alpha * (sum_k A[r][k] * W[c][k] + bias[c]),  A/W fp16, acc fp32.
// BM=128 BN=128 BK=32(halfs), 256 threads, 8 warps (2m x 4n), warp 64x32.
// Row stride 40 halfs = 20 words -> identical conflict-free pattern as R8.
// ---------------------------------------------------------------------------
#define BM 128
#define BN 128
#define BKH 32                          /* halfs per k-tile */
#define KSTH 40                         /* halfs row stride (=20 words) */
#define NKT (EDIM / BKH)                /* 32 */
#define NSTG 4
#define STGH ((BM + BN) * KSTH)         /* 10240 halfs = 20 KB per stage */
#define GEMM_SMEM (NSTG * STGH * 2)     /* 81920 bytes */

struct GemmJob  { const __half* W; const float* bias; void* C; float alpha; };
struct GemmJobs { GemmJob j[3]; };

template<bool SCRAMBLE>
__global__ __launch_bounds__(256, 2)
void gemm_mma(const __half* __restrict__ A, GemmJobs jobs)
{
    const GemmJob job = jobs.j[blockIdx.z];
    const __half* __restrict__ W   = job.W;
    const float* __restrict__ bias = job.bias;
    const float alpha              = job.alpha;

    extern __shared__ __half shh[];
    const uint32_t sb = smem_u32(shh);
    const int tid  = threadIdx.x;
    const int lane = tid & 31, wid = tid >> 5;
    const int g = lane >> 2, t = lane & 3;
    const int wm = (wid >> 2) * 64;          // warp m offset: 0 / 64
    const int wn = (wid & 3) * 32;           // warp n offset: 0/32/64/96
    const int rbase = blockIdx.y * BM;
    const int cbase = blockIdx.x * BN;

    // fill stage s with k-tile kt: 256 rows x 64B = 1024 x 16B chunks
    auto fill = [&](int s, int kt) {
        const uint32_t stgA = sb + (uint32_t)(s * STGH) * 2u;
        const uint32_t stgB = stgA + (uint32_t)(BM * KSTH) * 2u;
#pragma unroll
        for (int j = 0; j < 2; j++) {
            const int idx = tid + j * 256;       // 0..511
            const int r = idx >> 2, f = idx & 3;
            cp_async16(stgA + (uint32_t)(r * KSTH) * 2u + (uint32_t)f * 16u,
                       A + (size_t)(rbase + r) * EDIM + kt * BKH + f * 8);
        }
#pragma unroll
        for (int j = 0; j < 2; j++) {
            const int idx = tid + j * 256;
            const int r = idx >> 2, f = idx & 3;
            cp_async16(stgB + (uint32_t)(r * KSTH) * 2u + (uint32_t)f * 16u,
                       W + (size_t)(cbase + r) * EDIM + kt * BKH + f * 8);
        }
        cp_commit();
    };

    float accf[4][4][4];
#pragma unroll
    for (int mt = 0; mt < 4; mt++)
#pragma unroll
        for (int nt = 0; nt < 4; nt++)
#pragma unroll
            for (int q = 0; q < 4; q++) accf[mt][nt][q] = 0.f;

    fill(0, 0);
    fill(1, 1);
    fill(2, 2);

#pragma unroll 1
    for (int kt = 0; kt < NKT; kt++) {
        const int s = kt & (NSTG - 1);
        if (kt < NKT - 2)       cp_wait<2>();
        else if (kt == NKT - 2) cp_wait<1>();
        else                    cp_wait<0>();
        __syncthreads();

        const uint32_t* asw = (const uint32_t*)(shh + s * STGH);
        const uint32_t* bsw = (const uint32_t*)(shh + s * STGH + BM * KSTH);
#pragma unroll
        for (int ks = 0; ks < 2; ks++) {         // two k16 steps cover BKH=32
            uint32_t af[4][4], bf[4][2];
#pragma unroll
            for (int mt = 0; mt < 4; mt++) {
                const uint32_t* p = asw + (wm + mt * 16 + g) * 20 + ks * 8 + t;
                af[mt][0] = p[0];          // (row g,   k 2t..2t+1)
                af[mt][1] = p[160];        // (row g+8, k 2t..2t+1)
                af[mt][2] = p[4];          // (row g,   k 2t+8..2t+9)
                af[mt][3] = p[164];        // (row g+8, k 2t+8..2t+9)
            }
#pragma unroll
            for (int nt = 0; nt < 4; nt++) {
                const uint32_t* p = bsw + (wn + nt * 8 + g) * 20 + ks * 8 + t;
                bf[nt][0] = p[0];          // (k 2t..2t+1,   n g)
                bf[nt][1] = p[4];          // (k 2t+8..2t+9, n g)
            }
#pragma unroll
            for (int mt = 0; mt < 4; mt++)
#pragma unroll
                for (int nt = 0; nt < 4; nt++)
                    mma_f16(accf[mt][nt], af[mt], bf[nt]);
        }

        if (kt + 3 < NKT) fill((kt + 3) & (NSTG - 1), kt + 3);
    }

    // epilogue: c0=(g,2t) c1=(g,2t+1) c2=(g+8,2t) c3=(g+8,2t+1)
#pragma unroll
    for (int nt = 0; nt < 4; nt++) {
        const int col = cbase + wn + nt * 8 + 2 * t;
        const float2 bb = *(const float2*)&bias[col];
#pragma unroll
        for (int mt = 0; mt < 4; mt++) {
#pragma unroll
            for (int h = 0; h < 2; h++) {
                const int r = rbase + wm + mt * 16 + g + h * 8;
                const float vx = alpha * (accf[mt][nt][h * 2 + 0] + bb.x);
                const float vy = alpha * (accf[mt][nt][h * 2 + 1] + bb.y);
                if (SCRAMBLE) {
                    // write Q/K/V as fp16 (quantization == MMA operand rounding)
                    __half* Ch = (__half*)job.C;
                    const int b_ = r >> 11;
                    const int n  = r & (NSEQ - 1);
                    const int gb = col >> 9;
                    const int mm = (col >> 6) & 7;
                    const int dd = col & 63;
                    const int flat = n * 8 + mm;
                    const int mp = flat >> 11;
                    const int np = flat & (NSEQ - 1);
                    *(__half2*)(Ch + ((size_t)((b_ * 2 + gb) * 8 + mp) * NSEQ + np) * DH + dd) =
                        __floats2half2_rn(vx, vy);
                } else {
                    float* Cf = (float*)job.C;
                    float2 v; v.x = vx; v.y = vy;
                    *(float2*)(Cf + (size_t)r * EDIM + col) = v;
                }
            }
        }
    }
}

// ---------------------------------------------------------------------------
// Flash attention on fp16 HMMA m16n8k16. Br=128 (8 warps x m16), Bc=64,
// dh=64. cp.async double-buffered K/V; Q fragments in registers; P (fp16)
// smem round-trip; V natural layout, B-frags via 2x LDS.U16 + pack.
// ---------------------------------------------------------------------------
#define KSTRH 72          /* halfs row stride = 36 words: frag LDS bank-free */
#define VSTRH 72
#define PSTRH 72
#define OFF_K0 0
#define OFF_K1 (64 * KSTRH)                      /*  4608 halfs */
#define OFF_V0 (2 * 64 * KSTRH)                  /*  9216 */
#define OFF_V1 (OFF_V0 + 64 * VSTRH)             /* 13824 */
#define OFF_QP (OFF_V0 + 2 * 64 * VSTRH)         /* 18432 */
#define ATTN_SMEM ((OFF_QP + 128 * PSTRH) * 2)   /* 55296 bytes */

__global__ __launch_bounds__(256, 2)
void attn_mma(__half* __restrict__ ctx)
{
    extern __shared__ __half shh[];
    const uint32_t sb = smem_u32(shh);
    const int tid  = threadIdx.x;
    const int lane = tid & 31, wid = tid >> 5;
    const int g = lane >> 2, t = lane & 3;
    const int qblk = (int)gridDim.x - 1 - (int)blockIdx.x;   // long first
    const int bgm  = blockIdx.y;

    const __half* Qb = g_q + (size_t)bgm * NSEQ * DH;
    const __half* Kb = g_k + (size_t)bgm * NSEQ * DH;
    const __half* Vb = g_v + (size_t)bgm * NSEQ * DH;

    const uint32_t koff[2] = { OFF_K0 * 2u, OFF_K1 * 2u };
    const uint32_t voff[2] = { OFF_V0 * 2u, OFF_V1 * 2u };

    const int nkv = 2 * qblk + 2;

    // cp.async K/V tile 0 (64 rows x 128B each = 512 chunks per operand)
    {
#pragma unroll
        for (int i = 0; i < 2; i++) {
            const int idx = tid + i * 256;           // 0..511
            const int r = idx >> 3, f = idx & 7;
            cp_async16(sb + koff[0] + (uint32_t)(r * KSTRH) * 2u + (uint32_t)f * 16u,
                       Kb + (size_t)r * DH + f * 8);
        }
#pragma unroll
        for (int i = 0; i < 2; i++) {
            const int idx = tid + i * 256;
            const int r = idx >> 3, f = idx & 7;
            cp_async16(sb + voff[0] + (uint32_t)(r * VSTRH) * 2u + (uint32_t)f * 16u,
                       Vb + (size_t)r * DH + f * 8);
        }
        cp_commit();
    }

    // load Q tile (128 x 64 halfs) into QP
    {
        __half* QP = shh + OFF_QP;
#pragma unroll
        for (int i = 0; i < 4; i++) {
            const int idx = tid + i * 256;           // 0..1023
            const int r = idx >> 3, f = idx & 7;
            *(float4*)&QP[r * PSTRH + f * 8] =
                *(const float4*)(Qb + (size_t)(qblk * 128 + r) * DH + f * 8);
        }
    }
    __syncthreads();

    // Q A-fragments: 4 k16-steps x 4 regs
    uint32_t qf[4][4];
    {
        const uint32_t* QPw = (const uint32_t*)(shh + OFF_QP);
#pragma unroll
        for (int st = 0; st < 4; st++) {
            const uint32_t* p = QPw + (16 * wid + g) * 36 + st * 8 + t;
            qf[st][0] = p[0];
            qf[st][1] = p[288];       // +8 rows
            qf[st][2] = p[4];
            qf[st][3] = p[292];
        }
    }

    float m_i[2] = { -INFINITY, -INFINITY };
    float l_i[2] = { 0.f, 0.f };
    float Oa[8][4];
#pragma unroll
    for (int nt = 0; nt < 8; nt++)
#pragma unroll
        for (int q = 0; q < 4; q++) Oa[nt][q] = 0.f;

#pragma unroll 1
    for (int jb = 0; jb < nkv; jb++) {
        const int cur = jb & 1;
        cp_wait<0>();
        __syncthreads();

        if (jb + 1 < nkv) {
            const int nxt = (jb + 1) & 1;
            const __half* Ksrc = Kb + (size_t)(jb + 1) * 64 * DH;
            const __half* Vsrc = Vb + (size_t)(jb + 1) * 64 * DH;
#pragma unroll
            for (int i = 0; i < 2; i++) {
                const int idx = tid + i * 256;
                const int r = idx >> 3, f = idx & 7;
                cp_async16(sb + koff[nxt] + (uint32_t)(r * KSTRH) * 2u + (uint32_t)f * 16u,
                           Ksrc + (size_t)r * DH + f * 8);
            }
#pragma unroll
            for (int i = 0; i < 2; i++) {
                const int idx = tid + i * 256;
                const int r = idx >> 3, f = idx & 7;
                cp_async16(sb + voff[nxt] + (uint32_t)(r * VSTRH) * 2u + (uint32_t)f * 16u,
                           Vsrc + (size_t)r * DH + f * 8);
            }
            cp_commit();
        }

        const bool active = !(jb == 2 * qblk + 1 && wid < 4);
        if (active) {
            // ---- S = Q K^T ----
            float Sa[8][4];
#pragma unroll
            for (int nt = 0; nt < 8; nt++)
#pragma unroll
                for (int q = 0; q < 4; q++) Sa[nt][q] = 0.f;

            const uint32_t* Kw =
                (const uint32_t*)(shh + (cur ? OFF_K1 : OFF_K0));
#pragma unroll
            for (int nt = 0; nt < 8; nt++) {
#pragma unroll
                for (int st = 0; st < 4; st++) {
                    uint32_t bf[2];
                    const uint32_t* p = Kw + (nt * 8 + g) * 36 + st * 8 + t;
                    bf[0] = p[0];
                    bf[1] = p[4];
                    mma_f16(Sa[nt], qf[st], bf);
                }
            }

            // ---- causal mask ----
            if (jb >= 2 * qblk) {
                const int colb = jb * 64 + 2 * t;
                const int rowb = qblk * 128 + 16 * wid + g;
#pragma unroll
                for (int nt = 0; nt < 8; nt++) {
                    const int c0 = colb + nt * 8;
                    if (c0 > rowb)     Sa[nt][0] = -INFINITY;
                    if (c0 + 1 > rowb) Sa[nt][1] = -INFINITY;
                    if (c0 > rowb + 8)     Sa[nt][2] = -INFINITY;
                    if (c0 + 1 > rowb + 8) Sa[nt][3] = -INFINITY;
                }
            }

            // ---- online softmax ----
            __half* QP = shh + OFF_QP;
#pragma unroll
            for (int h = 0; h < 2; h++) {
                float rmax = -INFINITY;
#pragma unroll
                for (int nt = 0; nt < 8; nt++)
                    rmax = fmaxf(rmax, fmaxf(Sa[nt][2 * h], Sa[nt][2 * h + 1]));
                rmax = fmaxf(rmax, __shfl_xor_sync(0xffffffffu, rmax, 1));
                rmax = fmaxf(rmax, __shfl_xor_sync(0xffffffffu, rmax, 2));
                const float mnew = fmaxf(m_i[h], rmax);
                const float a = __expf(m_i[h] - mnew);
                float rs = 0.f;
#pragma unroll
                for (int nt = 0; nt < 8; nt++) {
                    const float p0 = __expf(Sa[nt][2 * h]     - mnew);
                    const float p1 = __expf(Sa[nt][2 * h + 1] - mnew);
                    Sa[nt][2 * h] = p0; Sa[nt][2 * h + 1] = p1;
                    rs += p0 + p1;
                }
                rs += __shfl_xor_sync(0xffffffffu, rs, 1);
                rs += __shfl_xor_sync(0xffffffffu, rs, 2);
                l_i[h] = l_i[h] * a + rs;
                m_i[h] = mnew;
#pragma unroll
                for (int nt = 0; nt < 8; nt++) {
                    Oa[nt][2 * h] *= a;
                    Oa[nt][2 * h + 1] *= a;
                }
                // store P row (fp16) to warp-private rows of QP
                const int prow = 16 * wid + g + 8 * h;
#pragma unroll
                for (int nt = 0; nt < 8; nt++) {
                    *(__half2*)&QP[prow * PSTRH + nt * 8 + 2 * t] =
                        __floats2half2_rn(Sa[nt][2 * h], Sa[nt][2 * h + 1]);
                }
            }
            __syncwarp();

            // ---- O += P V ----
            const uint32_t* Pw = (const uint32_t*)(shh + OFF_QP);
            const __half* Vh = shh + (cur ? OFF_V1 : OFF_V0);
#pragma unroll
            for (int st = 0; st < 4; st++) {
                uint32_t pa[4];
                const uint32_t* pp = Pw + (16 * wid + g) * 36 + st * 8 + t;
                pa[0] = pp[0];
                pa[1] = pp[288];
                pa[2] = pp[4];
                pa[3] = pp[292];
                const int k0 = st * 16 + 2 * t;
#pragma unroll
                for (int nt = 0; nt < 8; nt++) {
                    const int n = nt * 8 + g;
                    uint32_t bf[2];
                    {
                        const uint32_t lo = *(const uint16_t*)(Vh + (k0    ) * VSTRH + n);
                        const uint32_t hi = *(const uint16_t*)(Vh + (k0 + 1) * VSTRH + n);
                        bf[0] = lo | (hi << 16);
                    }
                    {
                        const uint32_t lo = *(const uint16_t*)(Vh + (k0 + 8) * VSTRH + n);
                        const uint32_t hi = *(const uint16_t*)(Vh + (k0 + 9) * VSTRH + n);
                        bf[1] = lo | (hi << 16);
                    }
                    mma_f16(Oa[nt], pa, bf);
                }
            }
        }
    }

    // epilogue: normalize, write ctx (fp16, feeds O-GEMM) UNSCRAMBLED
    const int b_ = bgm >> 4;
    const int gb = (bgm >> 3) & 1;
    const int mp = bgm & 7;
#pragma unroll
    for (int h = 0; h < 2; h++) {
        const float inv = 1.0f / l_i[h];
        const int np = qblk * 128 + 16 * wid + g + 8 * h;
        const int flat = mp * NSEQ + np;
        const int n  = flat >> 3;
        const int mm = flat & 7;
        const int colbase = gb * 512 + mm * 64 + 2 * t;
        __half* dst = ctx + (size_t)(b_ * NSEQ + n) * EDIM;
#pragma unroll
        for (int nt = 0; nt < 8; nt++) {
            *(__half2*)(dst + colbase + nt * 8) =
                __floats2half2_rn(Oa[nt][2 * h] * inv, Oa[nt][2 * h + 1] * inv);
        }
    }
}

// ---------------------------------------------------------------------------

extern "C" void kernel_launch(void* const* d_in, const int* in_sizes, int n_in,
                              void* d_out, int out_size) {
    (void)in_sizes; (void)n_in; (void)out_size;
    const float* x  = (const float*)d_in[0];
    const float* Wq = (const float*)d_in[1];
    const float* bq = (const float*)d_in[2];
    const float* Wk = (const float*)d_in[3];
    const float* bk = (const float*)d_in[4];
    const float* Wv = (const float*)d_in[5];
    const float* bv = (const float*)d_in[6];
    const float* Wo = (const float*)d_in[7];
    const float* bo = (const float*)d_in[8];
    float* out = (float*)d_out;

    __half *pq, *pk, *pv, *pctx, *pxh, *pwh;
    cudaGetSymbolAddress((void**)&pq,   g_q);
    cudaGetSymbolAddress((void**)&pk,   g_k);
    cudaGetSymbolAddress((void**)&pv,   g_v);
    cudaGetSymbolAddress((void**)&pctx, g_ctx);
    cudaGetSymbolAddress((void**)&pxh,  g_xh);
    cudaGetSymbolAddress((void**)&pwh,  g_wh);

    cudaFuncSetAttribute(gemm_mma<true>,
                         cudaFuncAttributeMaxDynamicSharedMemorySize, GEMM_SMEM);
    cudaFuncSetAttribute(gemm_mma<false>,
                         cudaFuncAttributeMaxDynamicSharedMemorySize, GEMM_SMEM);
    cudaFuncSetAttribute(attn_mma,
                         cudaFuncAttributeMaxDynamicSharedMemorySize, ATTN_SMEM);

    // 1) convert x and all W's to fp16 scratch
    precvt<<<2048, 256>>>((const float4*)x,
                          (const float4*)Wq, (const float4*)Wk,
                          (const float4*)Wv, (const float4*)Wo,
                          (uint2*)pxh, (uint2*)pwh);

    const float scale = 0.125f;  // dh^-0.5, folded into Q (and its bias)

    // 2) QKV projections (fused z-grid), fp16 in / fp16 scrambled out
    GemmJobs qkv;
    qkv.j[0] = { pwh + 0 * (size_t)EDIM * EDIM, bq, pq, scale };
    qkv.j[1] = { pwh + 1 * (size_t)EDIM * EDIM, bk, pk, 1.0f };
    qkv.j[2] = { pwh + 2 * (size_t)EDIM * EDIM, bv, pv, 1.0f };
    gemm_mma<true><<<dim3(EDIM / BN, (NBATCH * NSEQ) / BM, 3), 256, GEMM_SMEM>>>(pxh, qkv);

    // 3) attention (fp16 operands, fp32 softmax/accum)
    attn_mma<<<dim3(NSEQ / 128, NGROUPS), 256, ATTN_SMEM>>>(pctx);

    // 4) output projection: fp16 ctx x fp16 Wo -> fp32 out
    GemmJobs oj;
    oj.j[0] = { pwh + 3 * (size_t)EDIM * EDIM, bo, out, 1.0f };
    oj.j[1] = oj.j[0];
    oj.j[2] = oj.j[0];
    gemm_mma<false><<<dim3(EDIM / BN, (NBATCH * NSEQ) / BM, 1), 256, GEMM_SMEM>>>(pctx, oj);
}

// round 12
// speedup vs baseline: 5.5514x; 1.0284x over previous
#include <cuda_runtime.h>
#include <cuda_fp16.h>
#include <math.h>
#include <stdint.h>

#define EDIM 1024
#define NSEQ 2048
#define NBATCH 2
#define DH 64
#define NGROUPS 32   /* B * N_BLOCKS * MICRO_HEADS = 2*2*8 */

// Scratch (device globals: no allocation allowed in kernel_launch)
__device__ __half g_q[NGROUPS * NSEQ * DH];
__device__ __half g_k[NGROUPS * NSEQ * DH];
__device__ __half g_v[NGROUPS * NSEQ * DH];
__device__ __half g_ctx[NBATCH * NSEQ * EDIM];
__device__ __half g_xh[NBATCH * NSEQ * EDIM];   // fp16 x
__device__ __half g_wh[4 * EDIM * EDIM];        // fp16 Wq,Wk,Wv,Wo

// ---------------------------------------------------------------------------
// helpers
// ---------------------------------------------------------------------------
__device__ __forceinline__ void mma_f16(float* c, const uint32_t* a, const uint32_t* b) {
    asm volatile(
        "mma.sync.aligned.m16n8k16.row.col.f32.f16.f16.f32 "
        "{%0,%1,%2,%3}, {%4,%5,%6,%7}, {%8,%9}, {%0,%1,%2,%3};"
        : "+f"(c[0]), "+f"(c[1]), "+f"(c[2]), "+f"(c[3])
        : "r"(a[0]), "r"(a[1]), "r"(a[2]), "r"(a[3]), "r"(b[0]), "r"(b[1]));
}

__device__ __forceinline__ uint32_t smem_u32(const void* p) {
    uint32_t a;
    asm("{ .reg .u64 t; cvta.to.shared.u64 t, %1; cvt.u32.u64 %0, t; }" : "=r"(a) : "l"(p));
    return a;
}

__device__ __forceinline__ void cp_async16(uint32_t dst, const void* src) {
    asm volatile("cp.async.cg.shared.global [%0], [%1], 16;" :: "r"(dst), "l"(src));
}
__device__ __forceinline__ void cp_commit() {
    asm volatile("cp.async.commit_group;" ::: "memory");
}
template<int N>
__device__ __forceinline__ void cp_wait() {
    asm volatile("cp.async.wait_group %0;" :: "n"(N) : "memory");
}

// ---------------------------------------------------------------------------
// Pre-convert pass: x and all W's -> fp16 (RN).
// ---------------------------------------------------------------------------
#define XF4 (NBATCH * NSEQ * EDIM / 4)   /* 1048576 */
#define WF4 (EDIM * EDIM / 4)            /*  262144 */
#define TOTF4 (XF4 + 4 * WF4)

__global__ __launch_bounds__(256)
void precvt(const float4* __restrict__ x,
            const float4* __restrict__ wq, const float4* __restrict__ wk,
            const float4* __restrict__ wv, const float4* __restrict__ wo,
            uint2* __restrict__ xh, uint2* __restrict__ wh)
{
    for (int i = blockIdx.x * blockDim.x + threadIdx.x; i < TOTF4;
         i += gridDim.x * blockDim.x) {
        const float4* src;
        uint2* dst;
        if (i < XF4) {
            src = x + i; dst = xh + i;
        } else {
            const int j = i - XF4;
            const int w = j / WF4, o = j - w * WF4;
            const float4* ws = (w == 0) ? wq : (w == 1) ? wk : (w == 2) ? wv : wo;
            src = ws + o; dst = wh + j;
        }
        float4 v = *src;
        union { __half2 h2[2]; uint2 u; } cv;
        cv.h2[0] = __floats2half2_rn(v.x, v.y);
        cv.h2[1] = __floats2half2_rn(v.z, v.w);
        *dst = cv.u;
    }
}

// ---------------------------------------------------------------------------
// fp16 HMMA GEMM: occupancy-2, 3-stage cp.async pipeline, BK=64 halfs
// (4 k16-steps / 64 MMAs per warp between barriers).
// C[r][c] = alpha * (sum_k A[r][k] * W[c][k] + bias[c]),  A/W fp16, acc fp32.
// BM=128 BN=128, 256 threads, 8 warps (2m x 4n), warp 64x32.
// Row stride 72 halfs = 36 words -> fragment LDS conflict-free.
// ---------------------------------------------------------------------------
#define BM 128
#define BN 128
#define BKH 64                          /* halfs per k-tile */
#define KSTH 72                         /* halfs row stride (=36 words) */
#define NKT (EDIM / BKH)                /* 16 */
#define NSTG 3
#define STGH ((BM + BN) * KSTH)         /* 18432 halfs = 36864 B per stage */
#define GEMM_SMEM (NSTG * STGH * 2)     /* 110592 bytes */

struct GemmJob  { const __half* W; const float* bias; void* C; float alpha; };
struct GemmJobs { GemmJob j[3]; };

template<bool SCRAMBLE>
__global__ __launch_bounds__(256, 2)
void gemm_mma(const __half* __restrict__ A, GemmJobs jobs)
{
    const GemmJob job = jobs.j[blockIdx.z];
    const __half* __restrict__ W   = job.W;
    const float* __restrict__ bias = job.bias;
    const float alpha              = job.alpha;

    extern __shared__ __half shh[];
    const uint32_t sb = smem_u32(shh);
    const int tid  = threadIdx.x;
    const int lane = tid & 31, wid = tid >> 5;
    const int g = lane >> 2, t = lane & 3;
    const int wm = (wid >> 2) * 64;          // warp m offset: 0 / 64
    const int wn = (wid & 3) * 32;           // warp n offset: 0/32/64/96
    const int rbase = blockIdx.y * BM;
    const int cbase = blockIdx.x * BN;

    // fill stage s with k-tile kt: A 128 rows x 128B + B 128 rows x 128B
    auto fill = [&](int s, int kt) {
        const uint32_t stgA = sb + (uint32_t)(s * STGH) * 2u;
        const uint32_t stgB = stgA + (uint32_t)(BM * KSTH) * 2u;
#pragma unroll
        for (int j = 0; j < 4; j++) {
            const int idx = tid + j * 256;       // 0..1023
            const int r = idx >> 3, f = idx & 7;
            cp_async16(stgA + (uint32_t)(r * KSTH) * 2u + (uint32_t)f * 16u,
                       A + (size_t)(rbase + r) * EDIM + kt * BKH + f * 8);
        }
#pragma unroll
        for (int j = 0; j < 4; j++) {
            const int idx = tid + j * 256;
            const int r = idx >> 3, f = idx & 7;
            cp_async16(stgB + (uint32_t)(r * KSTH) * 2u + (uint32_t)f * 16u,
                       W + (size_t)(cbase + r) * EDIM + kt * BKH + f * 8);
        }
        cp_commit();
    };

    float accf[4][4][4];
#pragma unroll
    for (int mt = 0; mt < 4; mt++)
#pragma unroll
        for (int nt = 0; nt < 4; nt++)
#pragma unroll
            for (int q = 0; q < 4; q++) accf[mt][nt][q] = 0.f;

    fill(0, 0);
    fill(1, 1);

#pragma unroll 1
    for (int kt = 0; kt < NKT; kt++) {
        const int s = (kt % NSTG);
        if (kt == NKT - 1) cp_wait<0>();
        else               cp_wait<1>();
        __syncthreads();

        const uint32_t* asw = (const uint32_t*)(shh + s * STGH);
        const uint32_t* bsw = (const uint32_t*)(shh + s * STGH + BM * KSTH);
#pragma unroll
        for (int ks = 0; ks < 4; ks++) {         // four k16 steps cover BKH=64
            uint32_t af[4][4], bf[4][2];
#pragma unroll
            for (int mt = 0; mt < 4; mt++) {
                const uint32_t* p = asw + (wm + mt * 16 + g) * 36 + ks * 8 + t;
                af[mt][0] = p[0];          // (row g,   k 2t..2t+1)
                af[mt][1] = p[288];        // (row g+8)
                af[mt][2] = p[4];          // (row g,   k 2t+8..2t+9)
                af[mt][3] = p[292];
            }
#pragma unroll
            for (int nt = 0; nt < 4; nt++) {
                const uint32_t* p = bsw + (wn + nt * 8 + g) * 36 + ks * 8 + t;
                bf[nt][0] = p[0];
                bf[nt][1] = p[4];
            }
#pragma unroll
            for (int mt = 0; mt < 4; mt++)
#pragma unroll
                for (int nt = 0; nt < 4; nt++)
                    mma_f16(accf[mt][nt], af[mt], bf[nt]);
        }

        if (kt + 2 < NKT) fill((kt + 2) % NSTG, kt + 2);
    }

    // epilogue: c0=(g,2t) c1=(g,2t+1) c2=(g+8,2t) c3=(g+8,2t+1)
#pragma unroll
    for (int nt = 0; nt < 4; nt++) {
        const int col = cbase + wn + nt * 8 + 2 * t;
        const float2 bb = *(const float2*)&bias[col];
#pragma unroll
        for (int mt = 0; mt < 4; mt++) {
#pragma unroll
            for (int h = 0; h < 2; h++) {
                const int r = rbase + wm + mt * 16 + g + h * 8;
                const float vx = alpha * (accf[mt][nt][h * 2 + 0] + bb.x);
                const float vy = alpha * (accf[mt][nt][h * 2 + 1] + bb.y);
                if (SCRAMBLE) {
                    __half* Ch = (__half*)job.C;
                    const int b_ = r >> 11;
                    const int n  = r & (NSEQ - 1);
                    const int gb = col >> 9;
                    const int mm = (col >> 6) & 7;
                    const int dd = col & 63;
                    const int flat = n * 8 + mm;
                    const int mp = flat >> 11;
                    const int np = flat & (NSEQ - 1);
                    *(__half2*)(Ch + ((size_t)((b_ * 2 + gb) * 8 + mp) * NSEQ + np) * DH + dd) =
                        __floats2half2_rn(vx, vy);
                } else {
                    float* Cf = (float*)job.C;
                    float2 v; v.x = vx; v.y = vy;
                    *(float2*)(Cf + (size_t)r * EDIM + col) = v;
                }
            }
        }
    }
}

// ---------------------------------------------------------------------------
// Flash attention on fp16 HMMA m16n8k16. Br=128 (8 warps x m16), dh=64.
// KV loaded in 128-row tiles (double-buffered cp.async), processed as two
// 64-column halves with the proven inner loop (jb = 2*jt + half).
// ---------------------------------------------------------------------------
#define KSTRH 72          /* halfs row stride = 36 words */
#define VSTRH 72
#define PSTRH 72
#define OFF_K0 0
#define OFF_K1 (128 * KSTRH)                     /*  9216 halfs */
#define OFF_V0 (2 * 128 * KSTRH)                 /* 18432 */
#define OFF_V1 (OFF_V0 + 128 * VSTRH)            /* 27648 */
#define OFF_QP (OFF_V0 + 2 * 128 * VSTRH)        /* 36864 */
#define ATTN_SMEM ((OFF_QP + 128 * PSTRH) * 2)   /* 92160 bytes */

__global__ __launch_bounds__(256, 2)
void attn_mma(__half* __restrict__ ctx)
{
    extern __shared__ __half shh[];
    const uint32_t sb = smem_u32(shh);
    const int tid  = threadIdx.x;
    const int lane = tid & 31, wid = tid >> 5;
    const int g = lane >> 2, t = lane & 3;
    const int qblk = (int)gridDim.x - 1 - (int)blockIdx.x;   // long first
    const int bgm  = blockIdx.y;

    const __half* Qb = g_q + (size_t)bgm * NSEQ * DH;
    const __half* Kb = g_k + (size_t)bgm * NSEQ * DH;
    const __half* Vb = g_v + (size_t)bgm * NSEQ * DH;

    const uint32_t koff[2] = { OFF_K0 * 2u, OFF_K1 * 2u };
    const uint32_t voff[2] = { OFF_V0 * 2u, OFF_V1 * 2u };

    const int njb = qblk + 1;    // 128-row kv tiles (incl. diagonal)

    // cp.async K/V tile 0 (128 rows x 128B each = 1024 chunks per operand)
    {
#pragma unroll
        for (int i = 0; i < 4; i++) {
            const int idx = tid + i * 256;           // 0..1023
            const int r = idx >> 3, f = idx & 7;
            cp_async16(sb + koff[0] + (uint32_t)(r * KSTRH) * 2u + (uint32_t)f * 16u,
                       Kb + (size_t)r * DH + f * 8);
        }
#pragma unroll
        for (int i = 0; i < 4; i++) {
            const int idx = tid + i * 256;
            const int r = idx >> 3, f = idx & 7;
            cp_async16(sb + voff[0] + (uint32_t)(r * VSTRH) * 2u + (uint32_t)f * 16u,
                       Vb + (size_t)r * DH + f * 8);
        }
        cp_commit();
    }

    // load Q tile (128 x 64 halfs) into QP
    {
        __half* QP = shh + OFF_QP;
#pragma unroll
        for (int i = 0; i < 4; i++) {
            const int idx = tid + i * 256;           // 0..1023
            const int r = idx >> 3, f = idx & 7;
            *(float4*)&QP[r * PSTRH + f * 8] =
                *(const float4*)(Qb + (size_t)(qblk * 128 + r) * DH + f * 8);
        }
    }
    __syncthreads();

    // Q A-fragments: 4 k16-steps x 4 regs
    uint32_t qf[4][4];
    {
        const uint32_t* QPw = (const uint32_t*)(shh + OFF_QP);
#pragma unroll
        for (int st = 0; st < 4; st++) {
            const uint32_t* p = QPw + (16 * wid + g) * 36 + st * 8 + t;
            qf[st][0] = p[0];
            qf[st][1] = p[288];       // +8 rows
            qf[st][2] = p[4];
            qf[st][3] = p[292];
        }
    }

    float m_i[2] = { -INFINITY, -INFINITY };
    float l_i[2] = { 0.f, 0.f };
    float Oa[8][4];
#pragma unroll
    for (int nt = 0; nt < 8; nt++)
#pragma unroll
        for (int q = 0; q < 4; q++) Oa[nt][q] = 0.f;

#pragma unroll 1
    for (int jt = 0; jt < njb; jt++) {
        const int cur = jt & 1;
        cp_wait<0>();
        __syncthreads();

        if (jt + 1 < njb) {
            const int nxt = (jt + 1) & 1;
            const __half* Ksrc = Kb + (size_t)(jt + 1) * 128 * DH;
            const __half* Vsrc = Vb + (size_t)(jt + 1) * 128 * DH;
#pragma unroll
            for (int i = 0; i < 4; i++) {
                const int idx = tid + i * 256;
                const int r = idx >> 3, f = idx & 7;
                cp_async16(sb + koff[nxt] + (uint32_t)(r * KSTRH) * 2u + (uint32_t)f * 16u,
                           Ksrc + (size_t)r * DH + f * 8);
            }
#pragma unroll
            for (int i = 0; i < 4; i++) {
                const int idx = tid + i * 256;
                const int r = idx >> 3, f = idx & 7;
                cp_async16(sb + voff[nxt] + (uint32_t)(r * VSTRH) * 2u + (uint32_t)f * 16u,
                           Vsrc + (size_t)r * DH + f * 8);
            }
            cp_commit();
        }

#pragma unroll 1
        for (int half = 0; half < 2; half++) {
            const int jb = 2 * jt + half;            // 64-col tile index
            // warps 0..3 fully masked on the upper diagonal 64-tile: skip
            const bool active = !(jb == 2 * qblk + 1 && wid < 4);
            if (active) {
                // ---- S = Q K^T ----
                float Sa[8][4];
#pragma unroll
                for (int nt = 0; nt < 8; nt++)
#pragma unroll
                    for (int q = 0; q < 4; q++) Sa[nt][q] = 0.f;

                const uint32_t* Kw = (const uint32_t*)
                    (shh + (cur ? OFF_K1 : OFF_K0) + half * 64 * KSTRH);
#pragma unroll
                for (int nt = 0; nt < 8; nt++) {
#pragma unroll
                    for (int st = 0; st < 4; st++) {
                        uint32_t bf[2];
                        const uint32_t* p = Kw + (nt * 8 + g) * 36 + st * 8 + t;
                        bf[0] = p[0];
                        bf[1] = p[4];
                        mma_f16(Sa[nt], qf[st], bf);
                    }
                }

                // ---- causal mask ----
                if (jb >= 2 * qblk) {
                    const int colb = jb * 64 + 2 * t;
                    const int rowb = qblk * 128 + 16 * wid + g;
#pragma unroll
                    for (int nt = 0; nt < 8; nt++) {
                        const int c0 = colb + nt * 8;
                        if (c0 > rowb)     Sa[nt][0] = -INFINITY;
                        if (c0 + 1 > rowb) Sa[nt][1] = -INFINITY;
                        if (c0 > rowb + 8)     Sa[nt][2] = -INFINITY;
                        if (c0 + 1 > rowb + 8) Sa[nt][3] = -INFINITY;
                    }
                }

                // ---- online softmax ----
                __half* QP = shh + OFF_QP;
#pragma unroll
                for (int h = 0; h < 2; h++) {
                    float rmax = -INFINITY;
#pragma unroll
                    for (int nt = 0; nt < 8; nt++)
                        rmax = fmaxf(rmax, fmaxf(Sa[nt][2 * h], Sa[nt][2 * h + 1]));
                    rmax = fmaxf(rmax, __shfl_xor_sync(0xffffffffu, rmax, 1));
                    rmax = fmaxf(rmax, __shfl_xor_sync(0xffffffffu, rmax, 2));
                    const float mnew = fmaxf(m_i[h], rmax);
                    const float a = __expf(m_i[h] - mnew);
                    float rs = 0.f;
#pragma unroll
                    for (int nt = 0; nt < 8; nt++) {
                        const float p0 = __expf(Sa[nt][2 * h]     - mnew);
                        const float p1 = __expf(Sa[nt][2 * h + 1] - mnew);
                        Sa[nt][2 * h] = p0; Sa[nt][2 * h + 1] = p1;
                        rs += p0 + p1;
                    }
                    rs += __shfl_xor_sync(0xffffffffu, rs, 1);
                    rs += __shfl_xor_sync(0xffffffffu, rs, 2);
                    l_i[h] = l_i[h] * a + rs;
                    m_i[h] = mnew;
#pragma unroll
                    for (int nt = 0; nt < 8; nt++) {
                        Oa[nt][2 * h] *= a;
                        Oa[nt][2 * h + 1] *= a;
                    }
                    const int prow = 16 * wid + g + 8 * h;
#pragma unroll
                    for (int nt = 0; nt < 8; nt++) {
                        *(__half2*)&QP[prow * PSTRH + nt * 8 + 2 * t] =
                            __floats2half2_rn(Sa[nt][2 * h], Sa[nt][2 * h + 1]);
                    }
                }
                __syncwarp();

                // ---- O += P V ----
                const uint32_t* Pw = (const uint32_t*)(shh + OFF_QP);
                const __half* Vh = shh + (cur ? OFF_V1 : OFF_V0) + half * 64 * VSTRH;
#pragma unroll
                for (int st = 0; st < 4; st++) {
                    uint32_t pa[4];
                    const uint32_t* pp = Pw + (16 * wid + g) * 36 + st * 8 + t;
                    pa[0] = pp[0];
                    pa[1] = pp[288];
                    pa[2] = pp[4];
                    pa[3] = pp[292];
                    const int k0 = st * 16 + 2 * t;
#pragma unroll
                    for (int nt = 0; nt < 8; nt++) {
                        const int n = nt * 8 + g;
                        uint32_t bf[2];
                        {
                            const uint32_t lo = *(const uint16_t*)(Vh + (k0    ) * VSTRH + n);
                            const uint32_t hi = *(const uint16_t*)(Vh + (k0 + 1) * VSTRH + n);
                            bf[0] = lo | (hi << 16);
                        }
                        {
                            const uint32_t lo = *(const uint16_t*)(Vh + (k0 + 8) * VSTRH + n);
                            const uint32_t hi = *(const uint16_t*)(Vh + (k0 + 9) * VSTRH + n);
                            bf[1] = lo | (hi << 16);
                        }
                        mma_f16(Oa[nt], pa, bf);
                    }
                }
            }
        }
    }

    // epilogue: normalize, write ctx (fp16, feeds O-GEMM) UNSCRAMBLED
    const int b_ = bgm >> 4;
    const int gb = (bgm >> 3) & 1;
    const int mp = bgm & 7;
#pragma unroll
    for (int h = 0; h < 2; h++) {
        const float inv = 1.0f / l_i[h];
        const int np = qblk * 128 + 16 * wid + g + 8 * h;
        const int flat = mp * NSEQ + np;
        const int n  = flat >> 3;
        const int mm = flat & 7;
        const int colbase = gb * 512 + mm * 64 + 2 * t;
        __half* dst = ctx + (size_t)(b_ * NSEQ + n) * EDIM;
#pragma unroll
        for (int nt = 0; nt < 8; nt++) {
            *(__half2*)(dst + colbase + nt * 8) =
                __floats2half2_rn(Oa[nt][2 * h] * inv, Oa[nt][2 * h + 1] * inv);
        }
    }
}

// ---------------------------------------------------------------------------

extern "C" void kernel_launch(void* const* d_in, const int* in_sizes, int n_in,
                              void* d_out, int out_size) {
    (void)in_sizes; (void)n_in; (void)out_size;
    const float* x  = (const float*)d_in[0];
    const float* Wq = (const float*)d_in[1];
    const float* bq = (const float*)d_in[2];
    const float* Wk = (const float*)d_in[3];
    const float* bk = (const float*)d_in[4];
    const float* Wv = (const float*)d_in[5];
    const float* bv = (const float*)d_in[6];
    const float* Wo = (const float*)d_in[7];
    const float* bo = (const float*)d_in[8];
    float* out = (float*)d_out;

    __half *pq, *pk, *pv, *pctx, *pxh, *pwh;
    cudaGetSymbolAddress((void**)&pq,   g_q);
    cudaGetSymbolAddress((void**)&pk,   g_k);
    cudaGetSymbolAddress((void**)&pv,   g_v);
    cudaGetSymbolAddress((void**)&pctx, g_ctx);
    cudaGetSymbolAddress((void**)&pxh,  g_xh);
    cudaGetSymbolAddress((void**)&pwh,  g_wh);

    cudaFuncSetAttribute(gemm_mma<true>,
                         cudaFuncAttributeMaxDynamicSharedMemorySize, GEMM_SMEM);
    cudaFuncSetAttribute(gemm_mma<false>,
                         cudaFuncAttributeMaxDynamicSharedMemorySize, GEMM_SMEM);
    cudaFuncSetAttribute(attn_mma,
                         cudaFuncAttributeMaxDynamicSharedMemorySize, ATTN_SMEM);

    // 1) convert x and all W's to fp16 scratch
    precvt<<<2048, 256>>>((const float4*)x,
                          (const float4*)Wq, (const float4*)Wk,
                          (const float4*)Wv, (const float4*)Wo,
                          (uint2*)pxh, (uint2*)pwh);

    const float scale = 0.125f;  // dh^-0.5, folded into Q (and its bias)

    // 2) QKV projections (fused z-grid), fp16 in / fp16 scrambled out
    GemmJobs qkv;
    qkv.j[0] = { pwh + 0 * (size_t)EDIM * EDIM, bq, pq, scale };
    qkv.j[1] = { pwh + 1 * (size_t)EDIM * EDIM, bk, pk, 1.0f };
    qkv.j[2] = { pwh + 2 * (size_t)EDIM * EDIM, bv, pv, 1.0f };
    gemm_mma<true><<<dim3(EDIM / BN, (NBATCH * NSEQ) / BM, 3), 256, GEMM_SMEM>>>(pxh, qkv);

    // 3) attention (fp16 operands, fp32 softmax/accum)
    attn_mma<<<dim3(NSEQ / 128, NGROUPS), 256, ATTN_SMEM>>>(pctx);

    // 4) output projection: fp16 ctx x fp16 Wo -> fp32 out
    GemmJobs oj;
    oj.j[0] = { pwh + 3 * (size_t)EDIM * EDIM, bo, out, 1.0f };
    oj.j[1] = oj.j[0];
    oj.j[2] = oj.j[0];
    gemm_mma<false><<<dim3(EDIM / BN, (NBATCH * NSEQ) / BM, 1), 256, GEMM_SMEM>>>(pctx, oj);
}

// round 13
// speedup vs baseline: 6.6318x; 1.1946x over previous
#include <cuda_runtime.h>
#include <cuda_fp16.h>
#include <math.h>
#include <stdint.h>

#define EDIM 1024
#define NSEQ 2048
#define NBATCH 2
#define DH 64
#define NGROUPS 32   /* B * N_BLOCKS * MICRO_HEADS = 2*2*8 */

// Scratch (device globals: no allocation allowed in kernel_launch)
__device__ __half g_q[NGROUPS * NSEQ * DH];
__device__ __half g_k[NGROUPS * NSEQ * DH];
__device__ __half g_v[NGROUPS * NSEQ * DH];
__device__ __half g_ctx[NBATCH * NSEQ * EDIM];
__device__ __half g_xh[NBATCH * NSEQ * EDIM];   // fp16 x
__device__ __half g_wh[4 * EDIM * EDIM];        // fp16 Wq,Wk,Wv,Wo

// ---------------------------------------------------------------------------
// helpers
// ---------------------------------------------------------------------------
__device__ __forceinline__ void mma_f16(float* c, const uint32_t* a, const uint32_t* b) {
    asm volatile(
        "mma.sync.aligned.m16n8k16.row.col.f32.f16.f16.f32 "
        "{%0,%1,%2,%3}, {%4,%5,%6,%7}, {%8,%9}, {%0,%1,%2,%3};"
        : "+f"(c[0]), "+f"(c[1]), "+f"(c[2]), "+f"(c[3])
        : "r"(a[0]), "r"(a[1]), "r"(a[2]), "r"(a[3]), "r"(b[0]), "r"(b[1]));
}

__device__ __forceinline__ void ldsm_x4(uint32_t* r, uint32_t addr) {
    asm volatile("ldmatrix.sync.aligned.m8n8.x4.shared.b16 {%0,%1,%2,%3}, [%4];"
                 : "=r"(r[0]), "=r"(r[1]), "=r"(r[2]), "=r"(r[3]) : "r"(addr));
}
__device__ __forceinline__ void ldsm_x4_trans(uint32_t* r, uint32_t addr) {
    asm volatile("ldmatrix.sync.aligned.m8n8.x4.trans.shared.b16 {%0,%1,%2,%3}, [%4];"
                 : "=r"(r[0]), "=r"(r[1]), "=r"(r[2]), "=r"(r[3]) : "r"(addr));
}

__device__ __forceinline__ uint32_t smem_u32(const void* p) {
    uint32_t a;
    asm("{ .reg .u64 t; cvta.to.shared.u64 t, %1; cvt.u32.u64 %0, t; }" : "=r"(a) : "l"(p));
    return a;
}

__device__ __forceinline__ void cp_async16(uint32_t dst, const void* src) {
    asm volatile("cp.async.cg.shared.global [%0], [%1], 16;" :: "r"(dst), "l"(src));
}
__device__ __forceinline__ void cp_commit() {
    asm volatile("cp.async.commit_group;" ::: "memory");
}
template<int N>
__device__ __forceinline__ void cp_wait() {
    asm volatile("cp.async.wait_group %0;" :: "n"(N) : "memory");
}

// ---------------------------------------------------------------------------
// Pre-convert pass: x and all W's -> fp16 (RN).
// ---------------------------------------------------------------------------
#define XF4 (NBATCH * NSEQ * EDIM / 4)   /* 1048576 */
#define WF4 (EDIM * EDIM / 4)            /*  262144 */
#define TOTF4 (XF4 + 4 * WF4)

__global__ __launch_bounds__(256)
void precvt(const float4* __restrict__ x,
            const float4* __restrict__ wq, const float4* __restrict__ wk,
            const float4* __restrict__ wv, const float4* __restrict__ wo,
            uint2* __restrict__ xh, uint2* __restrict__ wh)
{
    for (int i = blockIdx.x * blockDim.x + threadIdx.x; i < TOTF4;
         i += gridDim.x * blockDim.x) {
        const float4* src;
        uint2* dst;
        if (i < XF4) {
            src = x + i; dst = xh + i;
        } else {
            const int j = i - XF4;
            const int w = j / WF4, o = j - w * WF4;
            const float4* ws = (w == 0) ? wq : (w == 1) ? wk : (w == 2) ? wv : wo;
            src = ws + o; dst = wh + j;
        }
        float4 v = *src;
        union { __half2 h2[2]; uint2 u; } cv;
        cv.h2[0] = __floats2half2_rn(v.x, v.y);
        cv.h2[1] = __floats2half2_rn(v.z, v.w);
        *dst = cv.u;
    }
}

// ---------------------------------------------------------------------------
// fp16 HMMA GEMM: occupancy-2, 3-stage cp.async pipeline, BK=64 halfs,
// ldmatrix fragment loads (6 LDSM.x4 per ks-step vs 24 scalar LDS).
// C[r][c] = alpha * (sum_k A[r][k] * W[c][k] + bias[c]),  A/W fp16, acc fp32.
// BM=128 BN=128, 256 threads, 8 warps (2m x 4n), warp 64x32.
// Row stride 72 halfs = 144 B -> LDSM 16B-chunk phases 9r mod 8: conflict-free.
// ---------------------------------------------------------------------------
#define BM 128
#define BN 128
#define BKH 64                          /* halfs per k-tile */
#define KSTH 72                         /* halfs row stride (=144 B) */
#define NKT (EDIM / BKH)                /* 16 */
#define NSTG 3
#define STGH ((BM + BN) * KSTH)         /* 18432 halfs = 36864 B per stage */
#define GEMM_SMEM (NSTG * STGH * 2)     /* 110592 bytes */

struct GemmJob  { const __half* W; const float* bias; void* C; float alpha; };
struct GemmJobs { GemmJob j[3]; };

template<bool SCRAMBLE>
__global__ __launch_bounds__(256, 2)
void gemm_mma(const __half* __restrict__ A, GemmJobs jobs)
{
    const GemmJob job = jobs.j[blockIdx.z];
    const __half* __restrict__ W   = job.W;
    const float* __restrict__ bias = job.bias;
    const float alpha              = job.alpha;

    extern __shared__ __half shh[];
    const uint32_t sb = smem_u32(shh);
    const int tid  = threadIdx.x;
    const int lane = tid & 31, wid = tid >> 5;
    const int g = lane >> 2, t = lane & 3;
    const int wm = (wid >> 2) * 64;          // warp m offset: 0 / 64
    const int wn = (wid & 3) * 32;           // warp n offset: 0/32/64/96
    const int rbase = blockIdx.y * BM;
    const int cbase = blockIdx.x * BN;

    // ldmatrix lane-address components (constant across k-tiles)
    const int aRow   = (lane & 15);          // A x4: row within 16, hi-chunk by lane>>4
    const int aChunk = (lane >> 4) * 16;     // bytes
    const int bRow   = (lane & 7) + (lane >> 4) * 8;   // B x4: nt-pair rows
    const int bChunk = ((lane >> 3) & 1) * 16;

    auto fill = [&](int s, int kt) {
        const uint32_t stgA = sb + (uint32_t)(s * STGH) * 2u;
        const uint32_t stgB = stgA + (uint32_t)(BM * KSTH) * 2u;
#pragma unroll
        for (int j = 0; j < 4; j++) {
            const int idx = tid + j * 256;       // 0..1023
            const int r = idx >> 3, f = idx & 7;
            cp_async16(stgA + (uint32_t)(r * KSTH) * 2u + (uint32_t)f * 16u,
                       A + (size_t)(rbase + r) * EDIM + kt * BKH + f * 8);
        }
#pragma unroll
        for (int j = 0; j < 4; j++) {
            const int idx = tid + j * 256;
            const int r = idx >> 3, f = idx & 7;
            cp_async16(stgB + (uint32_t)(r * KSTH) * 2u + (uint32_t)f * 16u,
                       W + (size_t)(cbase + r) * EDIM + kt * BKH + f * 8);
        }
        cp_commit();
    };

    float accf[4][4][4];
#pragma unroll
    for (int mt = 0; mt < 4; mt++)
#pragma unroll
        for (int nt = 0; nt < 4; nt++)
#pragma unroll
            for (int q = 0; q < 4; q++) accf[mt][nt][q] = 0.f;

    fill(0, 0);
    fill(1, 1);

#pragma unroll 1
    for (int kt = 0; kt < NKT; kt++) {
        const int s = (kt % NSTG);
        if (kt == NKT - 1) cp_wait<0>();
        else               cp_wait<1>();
        __syncthreads();

        const uint32_t aBase = sb + (uint32_t)(s * STGH) * 2u;
        const uint32_t bBase = aBase + (uint32_t)(BM * KSTH) * 2u;
#pragma unroll
        for (int ks = 0; ks < 4; ks++) {         // four k16 steps cover BKH=64
            uint32_t af[4][4], bf[4][2];
#pragma unroll
            for (int mt = 0; mt < 4; mt++) {
                const uint32_t addr = aBase
                    + (uint32_t)((wm + mt * 16 + aRow) * KSTH) * 2u
                    + (uint32_t)(ks * 32 + aChunk);
                ldsm_x4(af[mt], addr);
            }
#pragma unroll
            for (int ntp = 0; ntp < 2; ntp++) {
                uint32_t r4[4];
                const uint32_t addr = bBase
                    + (uint32_t)((wn + ntp * 16 + bRow) * KSTH) * 2u
                    + (uint32_t)(ks * 32 + bChunk);
                ldsm_x4(r4, addr);
                bf[2 * ntp][0] = r4[0]; bf[2 * ntp][1] = r4[1];
                bf[2 * ntp + 1][0] = r4[2]; bf[2 * ntp + 1][1] = r4[3];
            }
#pragma unroll
            for (int mt = 0; mt < 4; mt++)
#pragma unroll
                for (int nt = 0; nt < 4; nt++)
                    mma_f16(accf[mt][nt], af[mt], bf[nt]);
        }

        if (kt + 2 < NKT) fill((kt + 2) % NSTG, kt + 2);
    }

    // epilogue: c0=(g,2t) c1=(g,2t+1) c2=(g+8,2t) c3=(g+8,2t+1)
#pragma unroll
    for (int nt = 0; nt < 4; nt++) {
        const int col = cbase + wn + nt * 8 + 2 * t;
        const float2 bb = *(const float2*)&bias[col];
#pragma unroll
        for (int mt = 0; mt < 4; mt++) {
#pragma unroll
            for (int h = 0; h < 2; h++) {
                const int r = rbase + wm + mt * 16 + g + h * 8;
                const float vx = alpha * (accf[mt][nt][h * 2 + 0] + bb.x);
                const float vy = alpha * (accf[mt][nt][h * 2 + 1] + bb.y);
                if (SCRAMBLE) {
                    __half* Ch = (__half*)job.C;
                    const int b_ = r >> 11;
                    const int n  = r & (NSEQ - 1);
                    const int gb = col >> 9;
                    const int mm = (col >> 6) & 7;
                    const int dd = col & 63;
                    const int flat = n * 8 + mm;
                    const int mp = flat >> 11;
                    const int np = flat & (NSEQ - 1);
                    *(__half2*)(Ch + ((size_t)((b_ * 2 + gb) * 8 + mp) * NSEQ + np) * DH + dd) =
                        __floats2half2_rn(vx, vy);
                } else {
                    float* Cf = (float*)job.C;
                    float2 v; v.x = vx; v.y = vy;
                    *(float2*)(Cf + (size_t)r * EDIM + col) = v;
                }
            }
        }
    }
}

// ---------------------------------------------------------------------------
// Flash attention on fp16 HMMA m16n8k16 with ldmatrix fragment loads.
// Br=128 (8 warps x m16), dh=64. KV in 128-row double-buffered tiles,
// processed as two 64-column halves. V frags via ldmatrix.x4.trans.
// ---------------------------------------------------------------------------
#define KSTRH 72          /* halfs row stride = 144 B */
#define VSTRH 72
#define PSTRH 72
#define OFF_K0 0
#define OFF_K1 (128 * KSTRH)                     /*  9216 halfs */
#define OFF_V0 (2 * 128 * KSTRH)                 /* 18432 */
#define OFF_V1 (OFF_V0 + 128 * VSTRH)            /* 27648 */
#define OFF_QP (OFF_V0 + 2 * 128 * VSTRH)        /* 36864 */
#define ATTN_SMEM ((OFF_QP + 128 * PSTRH) * 2)   /* 92160 bytes */

__global__ __launch_bounds__(256, 2)
void attn_mma(__half* __restrict__ ctx)
{
    extern __shared__ __half shh[];
    const uint32_t sb = smem_u32(shh);
    const int tid  = threadIdx.x;
    const int lane = tid & 31, wid = tid >> 5;
    const int g = lane >> 2, t = lane & 3;
    const int qblk = (int)gridDim.x - 1 - (int)blockIdx.x;   // long first
    const int bgm  = blockIdx.y;

    const __half* Qb = g_q + (size_t)bgm * NSEQ * DH;
    const __half* Kb = g_k + (size_t)bgm * NSEQ * DH;
    const __half* Vb = g_v + (size_t)bgm * NSEQ * DH;

    const uint32_t koff[2] = { OFF_K0 * 2u, OFF_K1 * 2u };
    const uint32_t voff[2] = { OFF_V0 * 2u, OFF_V1 * 2u };

    // ldmatrix lane-address components
    const int aRow   = (lane & 15);
    const int aChunk = (lane >> 4) * 16;
    const int bRow   = (lane & 7) + (lane >> 4) * 8;
    const int bChunk = ((lane >> 3) & 1) * 16;
    const int vRow   = (lane & 7) + ((lane >> 3) & 1) * 8;   // k within 16
    const int vChunk = (lane >> 4) * 16;                      // n halfs *2 bytes

    const int njb = qblk + 1;    // 128-row kv tiles (incl. diagonal)

    {
#pragma unroll
        for (int i = 0; i < 4; i++) {
            const int idx = tid + i * 256;           // 0..1023
            const int r = idx >> 3, f = idx & 7;
            cp_async16(sb + koff[0] + (uint32_t)(r * KSTRH) * 2u + (uint32_t)f * 16u,
                       Kb + (size_t)r * DH + f * 8);
        }
#pragma unroll
        for (int i = 0; i < 4; i++) {
            const int idx = tid + i * 256;
            const int r = idx >> 3, f = idx & 7;
            cp_async16(sb + voff[0] + (uint32_t)(r * VSTRH) * 2u + (uint32_t)f * 16u,
                       Vb + (size_t)r * DH + f * 8);
        }
        cp_commit();
    }

    // load Q tile (128 x 64 halfs) into QP
    {
        __half* QP = shh + OFF_QP;
#pragma unroll
        for (int i = 0; i < 4; i++) {
            const int idx = tid + i * 256;           // 0..1023
            const int r = idx >> 3, f = idx & 7;
            *(float4*)&QP[r * PSTRH + f * 8] =
                *(const float4*)(Qb + (size_t)(qblk * 128 + r) * DH + f * 8);
        }
    }
    __syncthreads();

    // Q A-fragments via ldmatrix: 4 k16-steps x 4 regs
    uint32_t qf[4][4];
    {
        const uint32_t qBase = sb + OFF_QP * 2u;
#pragma unroll
        for (int st = 0; st < 4; st++) {
            const uint32_t addr = qBase
                + (uint32_t)((16 * wid + aRow) * PSTRH) * 2u
                + (uint32_t)(st * 32 + aChunk);
            ldsm_x4(qf[st], addr);
        }
    }

    float m_i[2] = { -INFINITY, -INFINITY };
    float l_i[2] = { 0.f, 0.f };
    float Oa[8][4];
#pragma unroll
    for (int nt = 0; nt < 8; nt++)
#pragma unroll
        for (int q = 0; q < 4; q++) Oa[nt][q] = 0.f;

#pragma unroll 1
    for (int jt = 0; jt < njb; jt++) {
        const int cur = jt & 1;
        cp_wait<0>();
        __syncthreads();

        if (jt + 1 < njb) {
            const int nxt = (jt + 1) & 1;
            const __half* Ksrc = Kb + (size_t)(jt + 1) * 128 * DH;
            const __half* Vsrc = Vb + (size_t)(jt + 1) * 128 * DH;
#pragma unroll
            for (int i = 0; i < 4; i++) {
                const int idx = tid + i * 256;
                const int r = idx >> 3, f = idx & 7;
                cp_async16(sb + koff[nxt] + (uint32_t)(r * KSTRH) * 2u + (uint32_t)f * 16u,
                           Ksrc + (size_t)r * DH + f * 8);
            }
#pragma unroll
            for (int i = 0; i < 4; i++) {
                const int idx = tid + i * 256;
                const int r = idx >> 3, f = idx & 7;
                cp_async16(sb + voff[nxt] + (uint32_t)(r * VSTRH) * 2u + (uint32_t)f * 16u,
                           Vsrc + (size_t)r * DH + f * 8);
            }
            cp_commit();
        }

#pragma unroll 1
        for (int half = 0; half < 2; half++) {
            const int jb = 2 * jt + half;            // 64-col tile index
            const bool active = !(jb == 2 * qblk + 1 && wid < 4);
            if (active) {
                // ---- S = Q K^T ----
                float Sa[8][4];
#pragma unroll
                for (int nt = 0; nt < 8; nt++)
#pragma unroll
                    for (int q = 0; q < 4; q++) Sa[nt][q] = 0.f;

                const uint32_t kBase = sb + (cur ? OFF_K1 : OFF_K0) * 2u
                                     + (uint32_t)(half * 64 * KSTRH) * 2u;
#pragma unroll
                for (int st = 0; st < 4; st++) {
#pragma unroll
                    for (int ntp = 0; ntp < 4; ntp++) {
                        uint32_t r4[4];
                        const uint32_t addr = kBase
                            + (uint32_t)((ntp * 16 + bRow) * KSTRH) * 2u
                            + (uint32_t)(st * 32 + bChunk);
                        ldsm_x4(r4, addr);
                        mma_f16(Sa[2 * ntp], qf[st], r4);
                        mma_f16(Sa[2 * ntp + 1], qf[st], r4 + 2);
                    }
                }

                // ---- causal mask ----
                if (jb >= 2 * qblk) {
                    const int colb = jb * 64 + 2 * t;
                    const int rowb = qblk * 128 + 16 * wid + g;
#pragma unroll
                    for (int nt = 0; nt < 8; nt++) {
                        const int c0 = colb + nt * 8;
                        if (c0 > rowb)     Sa[nt][0] = -INFINITY;
                        if (c0 + 1 > rowb) Sa[nt][1] = -INFINITY;
                        if (c0 > rowb + 8)     Sa[nt][2] = -INFINITY;
                        if (c0 + 1 > rowb + 8) Sa[nt][3] = -INFINITY;
                    }
                }

                // ---- online softmax ----
                __half* QP = shh + OFF_QP;
#pragma unroll
                for (int h = 0; h < 2; h++) {
                    float rmax = -INFINITY;
#pragma unroll
                    for (int nt = 0; nt < 8; nt++)
                        rmax = fmaxf(rmax, fmaxf(Sa[nt][2 * h], Sa[nt][2 * h + 1]));
                    rmax = fmaxf(rmax, __shfl_xor_sync(0xffffffffu, rmax, 1));
                    rmax = fmaxf(rmax, __shfl_xor_sync(0xffffffffu, rmax, 2));
                    const float mnew = fmaxf(m_i[h], rmax);
                    const float a = __expf(m_i[h] - mnew);
                    float rs = 0.f;
#pragma unroll
                    for (int nt = 0; nt < 8; nt++) {
                        const float p0 = __expf(Sa[nt][2 * h]     - mnew);
                        const float p1 = __expf(Sa[nt][2 * h + 1] - mnew);
                        Sa[nt][2 * h] = p0; Sa[nt][2 * h + 1] = p1;
                        rs += p0 + p1;
                    }
                    rs += __shfl_xor_sync(0xffffffffu, rs, 1);
                    rs += __shfl_xor_sync(0xffffffffu, rs, 2);
                    l_i[h] = l_i[h] * a + rs;
                    m_i[h] = mnew;
#pragma unroll
                    for (int nt = 0; nt < 8; nt++) {
                        Oa[nt][2 * h] *= a;
                        Oa[nt][2 * h + 1] *= a;
                    }
                    const int prow = 16 * wid + g + 8 * h;
#pragma unroll
                    for (int nt = 0; nt < 8; nt++) {
                        *(__half2*)&QP[prow * PSTRH + nt * 8 + 2 * t] =
                            __floats2half2_rn(Sa[nt][2 * h], Sa[nt][2 * h + 1]);
                    }
                }
                __syncwarp();

                // ---- O += P V ----
                const uint32_t pBase = sb + OFF_QP * 2u;
                const uint32_t vBase = sb + (cur ? OFF_V1 : OFF_V0) * 2u
                                     + (uint32_t)(half * 64 * VSTRH) * 2u;
#pragma unroll
                for (int st = 0; st < 4; st++) {
                    uint32_t pa[4];
                    {
                        const uint32_t addr = pBase
                            + (uint32_t)((16 * wid + aRow) * PSTRH) * 2u
                            + (uint32_t)(st * 32 + aChunk);
                        ldsm_x4(pa, addr);
                    }
#pragma unroll
                    for (int ntp = 0; ntp < 4; ntp++) {
                        uint32_t vb[4];
                        const uint32_t addr = vBase
                            + (uint32_t)((st * 16 + vRow) * VSTRH) * 2u
                            + (uint32_t)((ntp * 16) * 2 + vChunk);
                        ldsm_x4_trans(vb, addr);
                        mma_f16(Oa[2 * ntp], pa, vb);
                        mma_f16(Oa[2 * ntp + 1], pa, vb + 2);
                    }
                }
            }
        }
    }

    // epilogue: normalize, write ctx (fp16, feeds O-GEMM) UNSCRAMBLED
    const int b_ = bgm >> 4;
    const int gb = (bgm >> 3) & 1;
    const int mp = bgm & 7;
#pragma unroll
    for (int h = 0; h < 2; h++) {
        const float inv = 1.0f / l_i[h];
        const int np = qblk * 128 + 16 * wid + g + 8 * h;
        const int flat = mp * NSEQ + np;
        const int n  = flat >> 3;
        const int mm = flat & 7;
        const int colbase = gb * 512 + mm * 64 + 2 * t;
        __half* dst = ctx + (size_t)(b_ * NSEQ + n) * EDIM;
#pragma unroll
        for (int nt = 0; nt < 8; nt++) {
            *(__half2*)(dst + colbase + nt * 8) =
                __floats2half2_rn(Oa[nt][2 * h] * inv, Oa[nt][2 * h + 1] * inv);
        }
    }
}

// ---------------------------------------------------------------------------

extern "C" void kernel_launch(void* const* d_in, const int* in_sizes, int n_in,
                              void* d_out, int out_size) {
    (void)in_sizes; (void)n_in; (void)out_size;
    const float* x  = (const float*)d_in[0];
    const float* Wq = (const float*)d_in[1];
    const float* bq = (const float*)d_in[2];
    const float* Wk = (const float*)d_in[3];
    const float* bk = (const float*)d_in[4];
    const float* Wv = (const float*)d_in[5];
    const float* bv = (const float*)d_in[6];
    const float* Wo = (const float*)d_in[7];
    const float* bo = (const float*)d_in[8];
    float* out = (float*)d_out;

    __half *pq, *pk, *pv, *pctx, *pxh, *pwh;
    cudaGetSymbolAddress((void**)&pq,   g_q);
    cudaGetSymbolAddress((void**)&pk,   g_k);
    cudaGetSymbolAddress((void**)&pv,   g_v);
    cudaGetSymbolAddress((void**)&pctx, g_ctx);
    cudaGetSymbolAddress((void**)&pxh,  g_xh);
    cudaGetSymbolAddress((void**)&pwh,  g_wh);

    cudaFuncSetAttribute(gemm_mma<true>,
                         cudaFuncAttributeMaxDynamicSharedMemorySize, GEMM_SMEM);
    cudaFuncSetAttribute(gemm_mma<false>,
                         cudaFuncAttributeMaxDynamicSharedMemorySize, GEMM_SMEM);
    cudaFuncSetAttribute(attn_mma,
                         cudaFuncAttributeMaxDynamicSharedMemorySize, ATTN_SMEM);

    // 1) convert x and all W's to fp16 scratch
    precvt<<<2048, 256>>>((const float4*)x,
                          (const float4*)Wq, (const float4*)Wk,
                          (const float4*)Wv, (const float4*)Wo,
                          (uint2*)pxh, (uint2*)pwh);

    const float scale = 0.125f;  // dh^-0.5, folded into Q (and its bias)

    // 2) QKV projections (fused z-grid), fp16 in / fp16 scrambled out
    GemmJobs qkv;
    qkv.j[0] = { pwh + 0 * (size_t)EDIM * EDIM, bq, pq, scale };
    qkv.j[1] = { pwh + 1 * (size_t)EDIM * EDIM, bk, pk, 1.0f };
    qkv.j[2] = { pwh + 2 * (size_t)EDIM * EDIM, bv, pv, 1.0f };
    gemm_mma<true><<<dim3(EDIM / BN, (NBATCH * NSEQ) / BM, 3), 256, GEMM_SMEM>>>(pxh, qkv);

    // 3) attention (fp16 operands, fp32 softmax/accum)
    attn_mma<<<dim3(NSEQ / 128, NGROUPS), 256, ATTN_SMEM>>>(pctx);

    // 4) output projection: fp16 ctx x fp16 Wo -> fp32 out
    GemmJobs oj;
    oj.j[0] = { pwh + 3 * (size_t)EDIM * EDIM, bo, out, 1.0f };
    oj.j[1] = oj.j[0];
    oj.j[2] = oj.j[0];
    gemm_mma<false><<<dim3(EDIM / BN, (NBATCH * NSEQ) / BM, 1), 256, GEMM_SMEM>>>(pctx, oj);
}